// round 2
// baseline (speedup 1.0000x reference)
#include <cuda_runtime.h>
#include <math.h>
#include <stdint.h>

#define HIDDEN 2048
#define NH 16
#define HD 128
#define BATCH 2
#define SEQ 2048
#define MROWS (BATCH*SEQ)

// Scratch (device globals — no allocation allowed)
__device__ float g_q[(size_t)BATCH*NH*SEQ*HD];     // (b,h,s,d)
__device__ float g_k[(size_t)BATCH*NH*SEQ*HD];     // (b,h,s,d)
__device__ float g_v[(size_t)BATCH*NH*SEQ*HD];     // (b,h,s,d)
__device__ float g_attn[(size_t)BATCH*SEQ*NH*HD];  // (b,s,h,d) == [4096,2048] row-major

// ---------------------------------------------------------------------------
// Helpers: tf32 conversion + mma
// ---------------------------------------------------------------------------
__device__ __forceinline__ unsigned f2tf32(float x) {
    unsigned u;
    asm("cvt.rna.tf32.f32 %0, %1;" : "=r"(u) : "f"(x));
    return u;
}

// (hi, lo) split: hi = tf32(x), lo = tf32(x - hi). hi·hi + hi·lo + lo·hi ≈ fp32.
__device__ __forceinline__ float2 split_tf32(float x) {
    unsigned h = f2tf32(x);
    float hf = __uint_as_float(h);
    float lo = x - hf;
    return make_float2(hf, __uint_as_float(f2tf32(lo)));
}

__device__ __forceinline__ void mma_tf32(float* c, const unsigned* a, const unsigned* b) {
    asm volatile(
        "mma.sync.aligned.m16n8k8.row.col.f32.tf32.tf32.f32 "
        "{%0,%1,%2,%3}, {%4,%5,%6,%7}, {%8,%9}, {%0,%1,%2,%3};"
        : "+f"(c[0]), "+f"(c[1]), "+f"(c[2]), "+f"(c[3])
        : "r"(a[0]), "r"(a[1]), "r"(a[2]), "r"(a[3]), "r"(b[0]), "r"(b[1]));
}

// ---------------------------------------------------------------------------
// Tensor-core SGEMM via 3xTF32: C[4096,2048] = A[4096,2048] * W[2048,2048]
// Block tile 128x128xBK16, 8 warps in 2(m) x 4(n), warp tile 64x32.
// Smem holds (hi,lo) float2 per element, converted once at tile-store time.
// MODE 0: row-major store. MODE 1: scatter to (b,h,s,d).
// ---------------------------------------------------------------------------
#define BK 16
#define S_STRIDE 130

template<int MODE>
__global__ __launch_bounds__(256) void gemm_tc(
    const float* __restrict__ A, const float* __restrict__ W, float* __restrict__ out)
{
    const int N = 2048, K = 2048;
    __shared__ float2 As2[BK][S_STRIDE];   // [k][m] (hi,lo)
    __shared__ float2 Bs2[BK][S_STRIDE];   // [k][n] (hi,lo)

    const int tid = threadIdx.x;
    const int lane = tid & 31;
    const int warpId = tid >> 5;
    const int warpM = warpId >> 2;         // 0..1
    const int warpN = warpId & 3;          // 0..3
    const int gr = lane >> 2;              // 0..7
    const int gc = lane & 3;               // 0..3

    const int rowBase = blockIdx.y * 128;
    const int colBase = blockIdx.x * 128;

    // Global load mapping: 2 float4 per thread per tile.
    // A: i4 -> r = i4>>2 (0..127), kq = i4&3 (k = 4*kq)
    // B: i4 -> kr = i4>>5 (0..15), nc = (i4&31)*4
    const int a_r0  = tid >> 1;            // combined with it: r = (tid + 256*it)>>2
    (void)a_r0;

    float acc[4][4][4];
#pragma unroll
    for (int mt = 0; mt < 4; mt++)
#pragma unroll
        for (int nt = 0; nt < 4; nt++)
#pragma unroll
            for (int e = 0; e < 4; e++) acc[mt][nt][e] = 0.f;

    float4 aReg[2], bReg[2];
    // preload k0 = 0
#pragma unroll
    for (int it = 0; it < 2; it++) {
        int i4 = tid + 256 * it;
        int r = i4 >> 2, kq = i4 & 3;
        aReg[it] = *(const float4*)(A + (size_t)(rowBase + r) * K + kq * 4);
        int kr = i4 >> 5, nc = (i4 & 31) << 2;
        bReg[it] = *(const float4*)(W + (size_t)kr * N + colBase + nc);
    }

    for (int k0 = 0; k0 < K; k0 += BK) {
        // store regs -> smem with tf32 hi/lo split
#pragma unroll
        for (int it = 0; it < 2; it++) {
            int i4 = tid + 256 * it;
            int r = i4 >> 2, kq = i4 & 3;
            const float* av = (const float*)&aReg[it];
#pragma unroll
            for (int e = 0; e < 4; e++) As2[kq * 4 + e][r] = split_tf32(av[e]);
            int kr = i4 >> 5, nc = (i4 & 31) << 2;
            const float* bv = (const float*)&bReg[it];
#pragma unroll
            for (int e = 0; e < 4; e++) Bs2[kr][nc + e] = split_tf32(bv[e]);
        }
        __syncthreads();

        // prefetch next tile (overlaps with mma work below)
        int kn = k0 + BK;
        if (kn < K) {
#pragma unroll
            for (int it = 0; it < 2; it++) {
                int i4 = tid + 256 * it;
                int r = i4 >> 2, kq = i4 & 3;
                aReg[it] = *(const float4*)(A + (size_t)(rowBase + r) * K + kn + kq * 4);
                int kr = i4 >> 5, nc = (i4 & 31) << 2;
                bReg[it] = *(const float4*)(W + (size_t)(kn + kr) * N + colBase + nc);
            }
        }

#pragma unroll
        for (int k8 = 0; k8 < 2; k8++) {
            const int koff = k8 * 8;
            unsigned ahi[4][4], alo[4][4], bhi[4][2], blo[4][2];
#pragma unroll
            for (int mt = 0; mt < 4; mt++) {
                int r0 = warpM * 64 + mt * 16 + gr;
                float2 f0 = As2[koff + gc][r0];
                float2 f1 = As2[koff + gc][r0 + 8];
                float2 f2 = As2[koff + gc + 4][r0];
                float2 f3 = As2[koff + gc + 4][r0 + 8];
                ahi[mt][0] = __float_as_uint(f0.x); alo[mt][0] = __float_as_uint(f0.y);
                ahi[mt][1] = __float_as_uint(f1.x); alo[mt][1] = __float_as_uint(f1.y);
                ahi[mt][2] = __float_as_uint(f2.x); alo[mt][2] = __float_as_uint(f2.y);
                ahi[mt][3] = __float_as_uint(f3.x); alo[mt][3] = __float_as_uint(f3.y);
            }
#pragma unroll
            for (int nt = 0; nt < 4; nt++) {
                int n0 = warpN * 32 + nt * 8 + gr;
                float2 f0 = Bs2[koff + gc][n0];
                float2 f1 = Bs2[koff + gc + 4][n0];
                bhi[nt][0] = __float_as_uint(f0.x); blo[nt][0] = __float_as_uint(f0.y);
                bhi[nt][1] = __float_as_uint(f1.x); blo[nt][1] = __float_as_uint(f1.y);
            }
#pragma unroll
            for (int mt = 0; mt < 4; mt++)
#pragma unroll
                for (int nt = 0; nt < 4; nt++) {
                    mma_tf32(acc[mt][nt], ahi[mt], bhi[nt]);
                    mma_tf32(acc[mt][nt], ahi[mt], blo[nt]);
                    mma_tf32(acc[mt][nt], alo[mt], bhi[nt]);
                }
        }
        __syncthreads();
    }

    // epilogue
#pragma unroll
    for (int mt = 0; mt < 4; mt++) {
#pragma unroll
        for (int nt = 0; nt < 4; nt++) {
            int row0 = rowBase + warpM * 64 + mt * 16 + gr;
            int col0 = colBase + warpN * 32 + nt * 8 + 2 * gc;
#pragma unroll
            for (int half = 0; half < 2; half++) {
                int r = row0 + half * 8;
                float v0 = acc[mt][nt][2 * half];
                float v1 = acc[mt][nt][2 * half + 1];
                if (MODE == 0) {
                    out[(size_t)r * N + col0]     = v0;
                    out[(size_t)r * N + col0 + 1] = v1;
                } else {
                    int b = r >> 11, s = r & (SEQ - 1);
                    int h = col0 >> 7, d0 = col0 & (HD - 1);
                    float* p = out + (((size_t)b * NH + h) * SEQ + s) * HD + d0;
                    p[0] = v0;
                    p[1] = v1;
                }
            }
        }
    }
}

// ---------------------------------------------------------------------------
// RoPE (in place on (b,h,s,d) tensor).
// ---------------------------------------------------------------------------
__global__ __launch_bounds__(256) void rope_kernel(float* __restrict__ ten,
                                                   const int* __restrict__ pos_ids)
{
    int lane = threadIdx.x & 63;
    int rsub = threadIdx.x >> 6;
    int s = blockIdx.x * 4 + rsub;
    int bh = blockIdx.y;
    int pos = pos_ids[s];

    float t = powf(10000.0f, (float)(2 * lane) * (1.0f / 128.0f));
    float inv = 1.0f / t;
    float ang = (float)pos * inv;
    float sn, cs;
    sincosf(ang, &sn, &cs);

    float* p = ten + ((size_t)bh * SEQ + s) * HD;
    float x1 = p[lane];
    float x2 = p[lane + 64];
    p[lane]      = x1 * cs - x2 * sn;
    p[lane + 64] = x2 * cs + x1 * sn;
}

// ---------------------------------------------------------------------------
// Flash attention fp32, non-causal (unchanged from R1 — tensor-core version
// next round once HMMA throughput is measured).
// ---------------------------------------------------------------------------
#define QS_STRIDE 68
#define VS_STRIDE 132
#define PS_STRIDE 66
#define ATTN_SMEM_FLOATS (128*QS_STRIDE + 128*QS_STRIDE + 64*PS_STRIDE)

__global__ __launch_bounds__(256, 2) void attn_kernel(
    const float* __restrict__ Q, const float* __restrict__ K,
    const float* __restrict__ V, float* __restrict__ Out)
{
    extern __shared__ float smem[];
    float* qs  = smem;
    float* kvs = smem + 128 * QS_STRIDE;
    float* ps  = kvs + 128 * QS_STRIDE;

    const int tid = threadIdx.x;
    const int tx = tid & 15, ty = tid >> 4;
    const int qt = blockIdx.x;
    const int bh = blockIdx.y;

    const float* Qb = Q + ((size_t)bh * SEQ + qt * 64) * HD;
    const float* Kb = K + (size_t)bh * SEQ * HD;
    const float* Vb = V + (size_t)bh * SEQ * HD;

    {
        int r = tid & 63;
        int g0 = tid >> 6;
#pragma unroll
        for (int it = 0; it < 8; it++) {
            int dg = g0 + 4 * it;
            float4 v4 = *(const float4*)(Qb + (size_t)r * HD + dg * 4);
            qs[(dg * 4 + 0) * QS_STRIDE + r] = v4.x;
            qs[(dg * 4 + 1) * QS_STRIDE + r] = v4.y;
            qs[(dg * 4 + 2) * QS_STRIDE + r] = v4.z;
            qs[(dg * 4 + 3) * QS_STRIDE + r] = v4.w;
        }
    }

    float m[4], l[4], o[4][8];
#pragma unroll
    for (int i = 0; i < 4; i++) {
        m[i] = -1e30f; l[i] = 0.f;
#pragma unroll
        for (int j = 0; j < 8; j++) o[i][j] = 0.f;
    }

    const float SCALE = 0.08838834764831845f;
    const unsigned FULL = 0xffffffffu;

    __syncthreads();

    for (int t = 0; t < SEQ / 64; t++) {
        {
            int r = tid & 63;
            int g0 = tid >> 6;
            const float* Kt = Kb + (size_t)t * 64 * HD;
#pragma unroll
            for (int it = 0; it < 8; it++) {
                int dg = g0 + 4 * it;
                float4 v4 = *(const float4*)(Kt + (size_t)r * HD + dg * 4);
                kvs[(dg * 4 + 0) * QS_STRIDE + r] = v4.x;
                kvs[(dg * 4 + 1) * QS_STRIDE + r] = v4.y;
                kvs[(dg * 4 + 2) * QS_STRIDE + r] = v4.z;
                kvs[(dg * 4 + 3) * QS_STRIDE + r] = v4.w;
            }
        }
        __syncthreads();

        float sc[4][4];
#pragma unroll
        for (int i = 0; i < 4; i++)
#pragma unroll
            for (int j = 0; j < 4; j++) sc[i][j] = 0.f;

#pragma unroll 8
        for (int k = 0; k < 128; k++) {
            float ra[4], rb[4];
#pragma unroll
            for (int i = 0; i < 4; i++) ra[i] = qs[k * QS_STRIDE + ty + 16 * i];
#pragma unroll
            for (int j = 0; j < 4; j++) rb[j] = kvs[k * QS_STRIDE + tx + 16 * j];
#pragma unroll
            for (int i = 0; i < 4; i++)
#pragma unroll
                for (int j = 0; j < 4; j++)
                    sc[i][j] = fmaf(ra[i], rb[j], sc[i][j]);
        }
        __syncthreads();

        {
            const float* Vt = Vb + (size_t)t * 64 * HD;
#pragma unroll
            for (int it = 0; it < 8; it++) {
                int i4 = tid + 256 * it;
                int kv = i4 >> 5, dg = i4 & 31;
                float4 v4 = *(const float4*)(Vt + (size_t)kv * HD + dg * 4);
                *(float4*)&kvs[kv * VS_STRIDE + dg * 4] = v4;
            }
        }

#pragma unroll
        for (int i = 0; i < 4; i++) {
            float mx = fmaxf(fmaxf(sc[i][0], sc[i][1]), fmaxf(sc[i][2], sc[i][3]));
            mx = fmaxf(mx, __shfl_xor_sync(FULL, mx, 1));
            mx = fmaxf(mx, __shfl_xor_sync(FULL, mx, 2));
            mx = fmaxf(mx, __shfl_xor_sync(FULL, mx, 4));
            mx = fmaxf(mx, __shfl_xor_sync(FULL, mx, 8));
            mx *= SCALE;
            float mn = fmaxf(m[i], mx);
            float corr = __expf(m[i] - mn);
            m[i] = mn;
            float rs = 0.f;
#pragma unroll
            for (int j = 0; j < 4; j++) {
                float p = __expf(fmaf(sc[i][j], SCALE, -mn));
                ps[(ty + 16 * i) * PS_STRIDE + tx + 16 * j] = p;
                rs += p;
            }
            rs += __shfl_xor_sync(FULL, rs, 1);
            rs += __shfl_xor_sync(FULL, rs, 2);
            rs += __shfl_xor_sync(FULL, rs, 4);
            rs += __shfl_xor_sync(FULL, rs, 8);
            l[i] = l[i] * corr + rs;
#pragma unroll
            for (int j = 0; j < 8; j++) o[i][j] *= corr;
        }
        __syncthreads();

#pragma unroll 4
        for (int kk = 0; kk < 64; kk++) {
            float pa[4], vb[8];
#pragma unroll
            for (int i = 0; i < 4; i++) pa[i] = ps[(ty + 16 * i) * PS_STRIDE + kk];
#pragma unroll
            for (int j = 0; j < 8; j++) vb[j] = kvs[kk * VS_STRIDE + tx + 16 * j];
#pragma unroll
            for (int i = 0; i < 4; i++)
#pragma unroll
                for (int j = 0; j < 8; j++)
                    o[i][j] = fmaf(pa[i], vb[j], o[i][j]);
        }
        __syncthreads();
    }

    int b = bh >> 4, h = bh & 15;
#pragma unroll
    for (int i = 0; i < 4; i++) {
        int s = qt * 64 + ty + 16 * i;
        float inv_l = 1.0f / l[i];
#pragma unroll
        for (int j = 0; j < 8; j++) {
            int d = tx + 16 * j;
            Out[(((size_t)b * SEQ + s) * NH + h) * HD + d] = o[i][j] * inv_l;
        }
    }
}

// ---------------------------------------------------------------------------
extern "C" void kernel_launch(void* const* d_in, const int* in_sizes, int n_in,
                              void* d_out, int out_size)
{
    const float* hidden = (const float*)d_in[0];
    const int*   posids = (const int*)d_in[1];
    const float* wq     = (const float*)d_in[2];
    const float* wk     = (const float*)d_in[3];
    const float* wv     = (const float*)d_in[4];
    const float* wo     = (const float*)d_in[5];
    float* out = (float*)d_out;

    float *q, *k, *v, *attn;
    cudaGetSymbolAddress((void**)&q, g_q);
    cudaGetSymbolAddress((void**)&k, g_k);
    cudaGetSymbolAddress((void**)&v, g_v);
    cudaGetSymbolAddress((void**)&attn, g_attn);

    const size_t attn_smem = (size_t)ATTN_SMEM_FLOATS * sizeof(float);
    cudaFuncSetAttribute(attn_kernel, cudaFuncAttributeMaxDynamicSharedMemorySize,
                         (int)attn_smem);

    dim3 gemm_grid(2048 / 128, MROWS / 128);   // (16, 32)

    gemm_tc<1><<<gemm_grid, 256>>>(hidden, wq, q);
    gemm_tc<1><<<gemm_grid, 256>>>(hidden, wk, k);
    gemm_tc<1><<<gemm_grid, 256>>>(hidden, wv, v);

    dim3 rope_grid(SEQ / 4, BATCH * NH);
    rope_kernel<<<rope_grid, 256>>>(q, posids);
    rope_kernel<<<rope_grid, 256>>>(k, posids);

    dim3 attn_grid(SEQ / 64, BATCH * NH);
    attn_kernel<<<attn_grid, 256, attn_smem>>>(q, k, v, attn);

    gemm_tc<0><<<gemm_grid, 256>>>(attn, wo, out);
}

// round 4
// speedup vs baseline: 1.6932x; 1.6932x over previous
#include <cuda_runtime.h>
#include <cuda_bf16.h>
#include <math.h>
#include <stdint.h>

#define HIDDEN 2048
#define NH 16
#define HD 128
#define BATCH 2
#define SEQ 2048
#define MROWS (BATCH*SEQ)   // 4096

// ---------------- scratch (device globals; no allocation allowed) ----------
__device__ float g_q[(size_t)BATCH*NH*SEQ*HD];     // (b,h,s,d)
__device__ float g_k[(size_t)BATCH*NH*SEQ*HD];     // (b,h,s,d)
__device__ float g_v[(size_t)BATCH*NH*SEQ*HD];     // (b,h,s,d)
__device__ float g_attn[(size_t)BATCH*SEQ*NH*HD];  // (b,s,h,d) == [4096,2048]

__device__ __nv_bfloat16 g_ah[(size_t)MROWS*HIDDEN];      // A hi
__device__ __nv_bfloat16 g_al[(size_t)MROWS*HIDDEN];      // A lo
__device__ __nv_bfloat16 g_wh[4][(size_t)HIDDEN*HIDDEN];  // W^T hi (q,k,v,o)
__device__ __nv_bfloat16 g_wl[4][(size_t)HIDDEN*HIDDEN];  // W^T lo

// ---------------- PTX helpers ----------------------------------------------
__device__ __forceinline__ uint32_t smem_u32(const void* p) {
    uint32_t a;
    asm("{ .reg .u64 t; cvta.to.shared.u64 t, %1; cvt.u32.u64 %0, t; }" : "=r"(a) : "l"(p));
    return a;
}
__device__ __forceinline__ void cp16(uint32_t dst, const void* src) {
    asm volatile("cp.async.cg.shared.global [%0], [%1], 16;" :: "r"(dst), "l"(src));
}
__device__ __forceinline__ void cp_commit() { asm volatile("cp.async.commit_group;"); }

__device__ __forceinline__ void ldsm4(uint32_t* r, uint32_t addr) {
    asm volatile("ldmatrix.sync.aligned.m8n8.x4.shared.b16 {%0,%1,%2,%3}, [%4];"
                 : "=r"(r[0]), "=r"(r[1]), "=r"(r[2]), "=r"(r[3]) : "r"(addr));
}
__device__ __forceinline__ void mma_bf16(float* c, const uint32_t* a, uint32_t b0, uint32_t b1) {
    asm volatile(
        "mma.sync.aligned.m16n8k16.row.col.f32.bf16.bf16.f32 "
        "{%0,%1,%2,%3}, {%4,%5,%6,%7}, {%8,%9}, {%0,%1,%2,%3};"
        : "+f"(c[0]), "+f"(c[1]), "+f"(c[2]), "+f"(c[3])
        : "r"(a[0]), "r"(a[1]), "r"(a[2]), "r"(a[3]), "r"(b0), "r"(b1));
}

// ---------------- pack kernels ---------------------------------------------
__global__ __launch_bounds__(256) void pack_hl(const float* __restrict__ src,
                                               __nv_bfloat16* __restrict__ hi,
                                               __nv_bfloat16* __restrict__ lo)
{
    size_t i = ((size_t)blockIdx.x * 256 + threadIdx.x) * 4;
    float4 v = *(const float4*)(src + i);
    __nv_bfloat16 h[4], l[4];
    const float* f = (const float*)&v;
#pragma unroll
    for (int e = 0; e < 4; e++) {
        h[e] = __float2bfloat16_rn(f[e]);
        l[e] = __float2bfloat16_rn(f[e] - __bfloat162float(h[e]));
    }
    *(uint2*)(hi + i) = *(uint2*)h;
    *(uint2*)(lo + i) = *(uint2*)l;
}

// W [K=2048][N=2048] row-major  ->  Wt_hi/lo [N][K]
__global__ __launch_bounds__(256) void pack_wT(const float* __restrict__ W,
                                               __nv_bfloat16* __restrict__ th,
                                               __nv_bfloat16* __restrict__ tl)
{
    __shared__ float t[32][33];
    int n0 = blockIdx.x * 32, k0 = blockIdx.y * 32;
    int tx = threadIdx.x, ty = threadIdx.y;   // (32, 8)
#pragma unroll
    for (int j = 0; j < 4; j++)
        t[ty + 8 * j][tx] = W[(size_t)(k0 + ty + 8 * j) * HIDDEN + n0 + tx];
    __syncthreads();
#pragma unroll
    for (int j = 0; j < 4; j++) {
        float x = t[tx][ty + 8 * j];          // = W[k0+tx][n0+ty+8j]
        __nv_bfloat16 h = __float2bfloat16_rn(x);
        __nv_bfloat16 l = __float2bfloat16_rn(x - __bfloat162float(h));
        size_t o = (size_t)(n0 + ty + 8 * j) * HIDDEN + k0 + tx;
        th[o] = h;
        tl[o] = l;
    }
}

// ---------------- bf16 HMMA GEMM -------------------------------------------
// C[4096,2048] = A[4096,K=2048] * W[K,2048], B pre-transposed (Wt[n][k]).
// C = Ah*Bh + Ah*Bl + Al*Bh, fp32 accum.
// Block 128x128xBK32; 8 warps (2x4); warp tile 64x32.
// Smem rows of 32 bf16 padded to 40 (80B stride -> ldmatrix conflict-free).
#define GBK 32
#define ROWB 80                          // bytes per smem row (40 bf16)
#define T_A  (128 * ROWB)                // 10240 B per operand tile
#define OFF_AH 0
#define OFF_AL (1 * T_A)
#define OFF_BH (2 * T_A)
#define OFF_BL (3 * T_A)
#define STAGE  (4 * T_A)                 // 40960 B
#define GEMM_SMEM (2 * STAGE)            // 81920 B
#define NCH (HIDDEN / GBK)               // 64

template<int MODE>   // 0: row-major out, 1: scatter (b,h,s,d)
__global__ __launch_bounds__(256) void gemm_hmma(
    const __nv_bfloat16* __restrict__ Ahp, const __nv_bfloat16* __restrict__ Alp,
    const __nv_bfloat16* __restrict__ Bhp, const __nv_bfloat16* __restrict__ Blp,
    float* __restrict__ out)
{
    extern __shared__ char smem[];
    const uint32_t sb = smem_u32(smem);
    const int tid = threadIdx.x;
    const int lane = tid & 31;
    const int warpId = tid >> 5;
    const int warpM = warpId >> 2;       // 0..1
    const int warpN = warpId & 3;        // 0..3
    const int rowBase = blockIdx.y * 128;
    const int colBase = blockIdx.x * 128;

    const int lr = lane & 15;            // ldmatrix row within 16
    const int lc = lane >> 4;            // ldmatrix 8-col half

    float acc[4][4][4];
#pragma unroll
    for (int mt = 0; mt < 4; mt++)
#pragma unroll
        for (int nn = 0; nn < 4; nn++)
#pragma unroll
            for (int e = 0; e < 4; e++) acc[mt][nn][e] = 0.f;

    auto load_stage = [&](int buf, int chunk) {
        uint32_t base = sb + buf * STAGE;
        int kb = chunk * GBK;
#pragma unroll
        for (int i = 0; i < 2; i++) {
            int c4 = tid + 256 * i;
            int r = c4 >> 2, o = c4 & 3;
            uint32_t d = r * ROWB + o * 16;
            size_t sA = (size_t)(rowBase + r) * HIDDEN + kb + o * 8;
            size_t sB = (size_t)(colBase + r) * HIDDEN + kb + o * 8;
            cp16(base + OFF_AH + d, Ahp + sA);
            cp16(base + OFF_AL + d, Alp + sA);
            cp16(base + OFF_BH + d, Bhp + sB);
            cp16(base + OFF_BL + d, Blp + sB);
        }
        cp_commit();
    };

    load_stage(0, 0);
    load_stage(1, 1);

    for (int c = 0; c < NCH; c++) {
        if (c < NCH - 2) asm volatile("cp.async.wait_group 1;" ::: "memory");
        else             asm volatile("cp.async.wait_group 0;" ::: "memory");
        __syncthreads();

        uint32_t st = sb + (c & 1) * STAGE;
#pragma unroll
        for (int k16 = 0; k16 < 2; k16++) {
            const uint32_t kbyte = (k16 * 16 + lc * 8) * 2;
            uint32_t ah[4][4], al[4][4], bh[2][4], bl[2][4];
#pragma unroll
            for (int mt = 0; mt < 4; mt++) {
                uint32_t ro = (warpM * 64 + mt * 16 + lr) * ROWB + kbyte;
                ldsm4(ah[mt], st + OFF_AH + ro);
                ldsm4(al[mt], st + OFF_AL + ro);
            }
#pragma unroll
            for (int nt = 0; nt < 2; nt++) {
                uint32_t ro = (warpN * 32 + nt * 16 + lr) * ROWB + kbyte;
                ldsm4(bh[nt], st + OFF_BH + ro);
                ldsm4(bl[nt], st + OFF_BL + ro);
            }
#pragma unroll
            for (int mt = 0; mt < 4; mt++)
#pragma unroll
                for (int nn = 0; nn < 4; nn++) {
                    int nt = nn >> 1, hf = nn & 1;
                    mma_bf16(acc[mt][nn], ah[mt], bh[nt][hf], bh[nt][hf + 2]);
                    mma_bf16(acc[mt][nn], ah[mt], bl[nt][hf], bl[nt][hf + 2]);
                    mma_bf16(acc[mt][nn], al[mt], bh[nt][hf], bh[nt][hf + 2]);
                }
        }
        __syncthreads();
        if (c + 2 < NCH) load_stage(c & 1, c + 2);
    }

    // epilogue: lane j -> rows (j>>2, +8), cols (j&3)*2, +1
    const int er = lane >> 2, ec = (lane & 3) * 2;
#pragma unroll
    for (int mt = 0; mt < 4; mt++) {
#pragma unroll
        for (int nn = 0; nn < 4; nn++) {
            int col = colBase + warpN * 32 + nn * 8 + ec;
#pragma unroll
            for (int hf = 0; hf < 2; hf++) {
                int row = rowBase + warpM * 64 + mt * 16 + er + hf * 8;
                float v0 = acc[mt][nn][2 * hf];
                float v1 = acc[mt][nn][2 * hf + 1];
                if (MODE == 0) {
                    float2* p = (float2*)(out + (size_t)row * HIDDEN + col);
                    *p = make_float2(v0, v1);
                } else {
                    int b = row >> 11, s = row & (SEQ - 1);
                    int h = col >> 7, d = col & (HD - 1);
                    float2* p = (float2*)(out + (((size_t)b * NH + h) * SEQ + s) * HD + d);
                    *p = make_float2(v0, v1);
                }
            }
        }
    }
}

// ---------------- RoPE ------------------------------------------------------
__global__ __launch_bounds__(256) void rope_kernel(float* __restrict__ ten,
                                                   const int* __restrict__ pos_ids)
{
    int lane = threadIdx.x & 63;
    int rsub = threadIdx.x >> 6;
    int s = blockIdx.x * 4 + rsub;
    int bh = blockIdx.y;
    int pos = pos_ids[s];

    float t = powf(10000.0f, (float)(2 * lane) * (1.0f / 128.0f));
    float ang = (float)pos * (1.0f / t);
    float sn, cs;
    sincosf(ang, &sn, &cs);

    float* p = ten + ((size_t)bh * SEQ + s) * HD;
    float x1 = p[lane];
    float x2 = p[lane + 64];
    p[lane]      = x1 * cs - x2 * sn;
    p[lane + 64] = x2 * cs + x1 * sn;
}

// ---------------- Flash attention fp32 (validated R1) -----------------------
#define QS_STRIDE 68
#define VS_STRIDE 132
#define PS_STRIDE 66
#define ATTN_SMEM_FLOATS (128*QS_STRIDE + 128*QS_STRIDE + 64*PS_STRIDE)

__global__ __launch_bounds__(256, 2) void attn_kernel(
    const float* __restrict__ Q, const float* __restrict__ K,
    const float* __restrict__ V, float* __restrict__ Out)
{
    extern __shared__ float fsm[];
    float* qs  = fsm;
    float* kvs = fsm + 128 * QS_STRIDE;
    float* ps  = kvs + 128 * QS_STRIDE;

    const int tid = threadIdx.x;
    const int tx = tid & 15, ty = tid >> 4;
    const int qt = blockIdx.x;
    const int bh = blockIdx.y;

    const float* Qb = Q + ((size_t)bh * SEQ + qt * 64) * HD;
    const float* Kb = K + (size_t)bh * SEQ * HD;
    const float* Vb = V + (size_t)bh * SEQ * HD;

    {
        int r = tid & 63;
        int g0 = tid >> 6;
#pragma unroll
        for (int it = 0; it < 8; it++) {
            int dg = g0 + 4 * it;
            float4 v4 = *(const float4*)(Qb + (size_t)r * HD + dg * 4);
            qs[(dg * 4 + 0) * QS_STRIDE + r] = v4.x;
            qs[(dg * 4 + 1) * QS_STRIDE + r] = v4.y;
            qs[(dg * 4 + 2) * QS_STRIDE + r] = v4.z;
            qs[(dg * 4 + 3) * QS_STRIDE + r] = v4.w;
        }
    }

    float m[4], l[4], o[4][8];
#pragma unroll
    for (int i = 0; i < 4; i++) {
        m[i] = -1e30f; l[i] = 0.f;
#pragma unroll
        for (int j = 0; j < 8; j++) o[i][j] = 0.f;
    }

    const float SCALE = 0.08838834764831845f;
    const unsigned FULL = 0xffffffffu;

    __syncthreads();

    for (int t = 0; t < SEQ / 64; t++) {
        {
            int r = tid & 63;
            int g0 = tid >> 6;
            const float* Kt = Kb + (size_t)t * 64 * HD;
#pragma unroll
            for (int it = 0; it < 8; it++) {
                int dg = g0 + 4 * it;
                float4 v4 = *(const float4*)(Kt + (size_t)r * HD + dg * 4);
                kvs[(dg * 4 + 0) * QS_STRIDE + r] = v4.x;
                kvs[(dg * 4 + 1) * QS_STRIDE + r] = v4.y;
                kvs[(dg * 4 + 2) * QS_STRIDE + r] = v4.z;
                kvs[(dg * 4 + 3) * QS_STRIDE + r] = v4.w;
            }
        }
        __syncthreads();

        float sc[4][4];
#pragma unroll
        for (int i = 0; i < 4; i++)
#pragma unroll
            for (int j = 0; j < 4; j++) sc[i][j] = 0.f;

#pragma unroll 8
        for (int k = 0; k < 128; k++) {
            float ra[4], rb[4];
#pragma unroll
            for (int i = 0; i < 4; i++) ra[i] = qs[k * QS_STRIDE + ty + 16 * i];
#pragma unroll
            for (int j = 0; j < 4; j++) rb[j] = kvs[k * QS_STRIDE + tx + 16 * j];
#pragma unroll
            for (int i = 0; i < 4; i++)
#pragma unroll
                for (int j = 0; j < 4; j++)
                    sc[i][j] = fmaf(ra[i], rb[j], sc[i][j]);
        }
        __syncthreads();

        {
            const float* Vt = Vb + (size_t)t * 64 * HD;
#pragma unroll
            for (int it = 0; it < 8; it++) {
                int i4 = tid + 256 * it;
                int kv = i4 >> 5, dg = i4 & 31;
                float4 v4 = *(const float4*)(Vt + (size_t)kv * HD + dg * 4);
                *(float4*)&kvs[kv * VS_STRIDE + dg * 4] = v4;
            }
        }

#pragma unroll
        for (int i = 0; i < 4; i++) {
            float mx = fmaxf(fmaxf(sc[i][0], sc[i][1]), fmaxf(sc[i][2], sc[i][3]));
            mx = fmaxf(mx, __shfl_xor_sync(FULL, mx, 1));
            mx = fmaxf(mx, __shfl_xor_sync(FULL, mx, 2));
            mx = fmaxf(mx, __shfl_xor_sync(FULL, mx, 4));
            mx = fmaxf(mx, __shfl_xor_sync(FULL, mx, 8));
            mx *= SCALE;
            float mn = fmaxf(m[i], mx);
            float corr = __expf(m[i] - mn);
            m[i] = mn;
            float rs = 0.f;
#pragma unroll
            for (int j = 0; j < 4; j++) {
                float p = __expf(fmaf(sc[i][j], SCALE, -mn));
                ps[(ty + 16 * i) * PS_STRIDE + tx + 16 * j] = p;
                rs += p;
            }
            rs += __shfl_xor_sync(FULL, rs, 1);
            rs += __shfl_xor_sync(FULL, rs, 2);
            rs += __shfl_xor_sync(FULL, rs, 4);
            rs += __shfl_xor_sync(FULL, rs, 8);
            l[i] = l[i] * corr + rs;
#pragma unroll
            for (int j = 0; j < 8; j++) o[i][j] *= corr;
        }
        __syncthreads();

#pragma unroll 4
        for (int kk = 0; kk < 64; kk++) {
            float pa[4], vb[8];
#pragma unroll
            for (int i = 0; i < 4; i++) pa[i] = ps[(ty + 16 * i) * PS_STRIDE + kk];
#pragma unroll
            for (int j = 0; j < 8; j++) vb[j] = kvs[kk * VS_STRIDE + tx + 16 * j];
#pragma unroll
            for (int i = 0; i < 4; i++)
#pragma unroll
                for (int j = 0; j < 8; j++)
                    o[i][j] = fmaf(pa[i], vb[j], o[i][j]);
        }
        __syncthreads();
    }

    int b = bh >> 4, h = bh & 15;
#pragma unroll
    for (int i = 0; i < 4; i++) {
        int s = qt * 64 + ty + 16 * i;
        float inv_l = 1.0f / l[i];
#pragma unroll
        for (int j = 0; j < 8; j++) {
            int d = tx + 16 * j;
            Out[(((size_t)b * SEQ + s) * NH + h) * HD + d] = o[i][j] * inv_l;
        }
    }
}

// ---------------------------------------------------------------------------
extern "C" void kernel_launch(void* const* d_in, const int* in_sizes, int n_in,
                              void* d_out, int out_size)
{
    const float* hidden = (const float*)d_in[0];
    const int*   posids = (const int*)d_in[1];
    const float* wk_in[4] = { (const float*)d_in[2], (const float*)d_in[3],
                              (const float*)d_in[4], (const float*)d_in[5] };
    float* out = (float*)d_out;

    float *q, *k, *v, *attn;
    __nv_bfloat16 *ah, *al, *wh, *wl;
    cudaGetSymbolAddress((void**)&q, g_q);
    cudaGetSymbolAddress((void**)&k, g_k);
    cudaGetSymbolAddress((void**)&v, g_v);
    cudaGetSymbolAddress((void**)&attn, g_attn);
    cudaGetSymbolAddress((void**)&ah, g_ah);
    cudaGetSymbolAddress((void**)&al, g_al);
    cudaGetSymbolAddress((void**)&wh, g_wh);
    cudaGetSymbolAddress((void**)&wl, g_wl);
    const size_t wstep = (size_t)HIDDEN * HIDDEN;

    cudaFuncSetAttribute(gemm_hmma<0>, cudaFuncAttributeMaxDynamicSharedMemorySize, GEMM_SMEM);
    cudaFuncSetAttribute(gemm_hmma<1>, cudaFuncAttributeMaxDynamicSharedMemorySize, GEMM_SMEM);
    const size_t attn_smem = (size_t)ATTN_SMEM_FLOATS * sizeof(float);
    cudaFuncSetAttribute(attn_kernel, cudaFuncAttributeMaxDynamicSharedMemorySize, (int)attn_smem);

    // pack inputs
    pack_hl<<<(MROWS * HIDDEN) / 1024, 256>>>(hidden, ah, al);
    dim3 wg(HIDDEN / 32, HIDDEN / 32);
    for (int i = 0; i < 4; i++)
        pack_wT<<<wg, dim3(32, 8)>>>(wk_in[i], wh + i * wstep, wl + i * wstep);

    dim3 gg(HIDDEN / 128, MROWS / 128);   // (16, 32)

    // QKV projections
    gemm_hmma<1><<<gg, 256, GEMM_SMEM>>>(ah, al, wh + 0 * wstep, wl + 0 * wstep, q);
    gemm_hmma<1><<<gg, 256, GEMM_SMEM>>>(ah, al, wh + 1 * wstep, wl + 1 * wstep, k);
    gemm_hmma<1><<<gg, 256, GEMM_SMEM>>>(ah, al, wh + 2 * wstep, wl + 2 * wstep, v);

    // RoPE
    dim3 rg(SEQ / 4, BATCH * NH);
    rope_kernel<<<rg, 256>>>(q, posids);
    rope_kernel<<<rg, 256>>>(k, posids);

    // attention (fp32)
    dim3 ag(SEQ / 64, BATCH * NH);
    attn_kernel<<<ag, 256, attn_smem>>>(q, k, v, attn);

    // O projection
    pack_hl<<<(MROWS * HIDDEN) / 1024, 256>>>(attn, ah, al);
    gemm_hmma<0><<<gg, 256, GEMM_SMEM>>>(ah, al, wh + 3 * wstep, wl + 3 * wstep, out);
}

// round 5
// speedup vs baseline: 2.9045x; 1.7153x over previous
#include <cuda_runtime.h>
#include <cuda_bf16.h>
#include <math.h>
#include <stdint.h>

#define HIDDEN 2048
#define NH 16
#define HD 128
#define BATCH 2
#define SEQ 2048
#define MROWS (BATCH*SEQ)   // 4096

// 1/sqrt(128) * log2(e)  — folds softmax scale + nat->log2 into Q
#define QSC 0.1275174277f

// ---------------- scratch (device globals; no allocation allowed) ----------
__device__ float g_q[(size_t)BATCH*NH*SEQ*HD];     // (b,h,s,d) fp32
__device__ float g_k[(size_t)BATCH*NH*SEQ*HD];
__device__ float g_v[(size_t)BATCH*NH*SEQ*HD];

__device__ __nv_bfloat16 g_ah[(size_t)MROWS*HIDDEN];      // GEMM A hi
__device__ __nv_bfloat16 g_al[(size_t)MROWS*HIDDEN];      // GEMM A lo
__device__ __nv_bfloat16 g_wh[4][(size_t)HIDDEN*HIDDEN];  // W^T hi (q,k,v,o)
__device__ __nv_bfloat16 g_wl[4][(size_t)HIDDEN*HIDDEN];  // W^T lo

__device__ __nv_bfloat16 g_qh[(size_t)BATCH*NH*SEQ*HD];
__device__ __nv_bfloat16 g_ql[(size_t)BATCH*NH*SEQ*HD];
__device__ __nv_bfloat16 g_kh[(size_t)BATCH*NH*SEQ*HD];
__device__ __nv_bfloat16 g_kl[(size_t)BATCH*NH*SEQ*HD];
__device__ __nv_bfloat16 g_vh[(size_t)BATCH*NH*SEQ*HD];
__device__ __nv_bfloat16 g_vl[(size_t)BATCH*NH*SEQ*HD];

// ---------------- PTX helpers ----------------------------------------------
__device__ __forceinline__ uint32_t smem_u32(const void* p) {
    uint32_t a;
    asm("{ .reg .u64 t; cvta.to.shared.u64 t, %1; cvt.u32.u64 %0, t; }" : "=r"(a) : "l"(p));
    return a;
}
__device__ __forceinline__ void cp16(uint32_t dst, const void* src) {
    asm volatile("cp.async.cg.shared.global [%0], [%1], 16;" :: "r"(dst), "l"(src));
}
__device__ __forceinline__ void cp_commit() { asm volatile("cp.async.commit_group;"); }

__device__ __forceinline__ void ldsm4(uint32_t* r, uint32_t addr) {
    asm volatile("ldmatrix.sync.aligned.m8n8.x4.shared.b16 {%0,%1,%2,%3}, [%4];"
                 : "=r"(r[0]), "=r"(r[1]), "=r"(r[2]), "=r"(r[3]) : "r"(addr));
}
__device__ __forceinline__ void ldsm4t(uint32_t* r, uint32_t addr) {
    asm volatile("ldmatrix.sync.aligned.m8n8.x4.trans.shared.b16 {%0,%1,%2,%3}, [%4];"
                 : "=r"(r[0]), "=r"(r[1]), "=r"(r[2]), "=r"(r[3]) : "r"(addr));
}
__device__ __forceinline__ void mma_bf16(float* c, const uint32_t* a, uint32_t b0, uint32_t b1) {
    asm volatile(
        "mma.sync.aligned.m16n8k16.row.col.f32.bf16.bf16.f32 "
        "{%0,%1,%2,%3}, {%4,%5,%6,%7}, {%8,%9}, {%0,%1,%2,%3};"
        : "+f"(c[0]), "+f"(c[1]), "+f"(c[2]), "+f"(c[3])
        : "r"(a[0]), "r"(a[1]), "r"(a[2]), "r"(a[3]), "r"(b0), "r"(b1));
}
__device__ __forceinline__ uint32_t packbf(float lo, float hi) {
    uint32_t r;
    asm("cvt.rn.bf16x2.f32 %0, %1, %2;" : "=r"(r) : "f"(hi), "f"(lo));
    return r;
}
// fast 2^x on FMA pipe, x <= 0; relative error ~2.4e-6
__device__ __forceinline__ float exp2p(float x) {
    x = fmaxf(x, -120.0f);
    float n = rintf(x);
    float f = x - n;
    float p = fmaf(f, 0.0013333558f, 0.0096181291f);
    p = fmaf(f, p, 0.0555041087f);
    p = fmaf(f, p, 0.2402265070f);
    p = fmaf(f, p, 0.6931471806f);
    p = fmaf(f, p, 1.0f);
    return __int_as_float(__float_as_int(p) + ((int)n << 23));
}

// ---------------- pack kernels ---------------------------------------------
__global__ __launch_bounds__(256) void pack_hl(const float* __restrict__ src,
                                               __nv_bfloat16* __restrict__ hi,
                                               __nv_bfloat16* __restrict__ lo)
{
    size_t i = ((size_t)blockIdx.x * 256 + threadIdx.x) * 4;
    float4 v = *(const float4*)(src + i);
    __nv_bfloat16 h[4], l[4];
    const float* f = (const float*)&v;
#pragma unroll
    for (int e = 0; e < 4; e++) {
        h[e] = __float2bfloat16_rn(f[e]);
        l[e] = __float2bfloat16_rn(f[e] - __bfloat162float(h[e]));
    }
    *(uint2*)(hi + i) = *(uint2*)h;
    *(uint2*)(lo + i) = *(uint2*)l;
}

__global__ __launch_bounds__(256) void pack_wT(const float* __restrict__ W,
                                               __nv_bfloat16* __restrict__ th,
                                               __nv_bfloat16* __restrict__ tl)
{
    __shared__ float t[32][33];
    int n0 = blockIdx.x * 32, k0 = blockIdx.y * 32;
    int tx = threadIdx.x, ty = threadIdx.y;   // (32, 8)
#pragma unroll
    for (int j = 0; j < 4; j++)
        t[ty + 8 * j][tx] = W[(size_t)(k0 + ty + 8 * j) * HIDDEN + n0 + tx];
    __syncthreads();
#pragma unroll
    for (int j = 0; j < 4; j++) {
        float x = t[tx][ty + 8 * j];
        __nv_bfloat16 h = __float2bfloat16_rn(x);
        __nv_bfloat16 l = __float2bfloat16_rn(x - __bfloat162float(h));
        size_t o = (size_t)(n0 + ty + 8 * j) * HIDDEN + k0 + tx;
        th[o] = h;
        tl[o] = l;
    }
}

__global__ __launch_bounds__(256) void rope_pack(const float* __restrict__ src,
                                                 const int* __restrict__ pos_ids,
                                                 __nv_bfloat16* __restrict__ hi,
                                                 __nv_bfloat16* __restrict__ lo,
                                                 float scale)
{
    int lane = threadIdx.x & 63;
    int rsub = threadIdx.x >> 6;
    int s = blockIdx.x * 4 + rsub;
    int bh = blockIdx.y;
    int pos = pos_ids[s];

    float t = powf(10000.0f, (float)(2 * lane) * (1.0f / 128.0f));
    float ang = (float)pos * (1.0f / t);
    float sn, cs;
    sincosf(ang, &sn, &cs);

    const float* p = src + ((size_t)bh * SEQ + s) * HD;
    float x1 = p[lane];
    float x2 = p[lane + 64];
    float y1 = (x1 * cs - x2 * sn) * scale;
    float y2 = (x2 * cs + x1 * sn) * scale;

    size_t o = ((size_t)bh * SEQ + s) * HD;
    __nv_bfloat16 h1 = __float2bfloat16_rn(y1);
    __nv_bfloat16 h2 = __float2bfloat16_rn(y2);
    hi[o + lane]      = h1;
    hi[o + lane + 64] = h2;
    lo[o + lane]      = __float2bfloat16_rn(y1 - __bfloat162float(h1));
    lo[o + lane + 64] = __float2bfloat16_rn(y2 - __bfloat162float(h2));
}

// ---------------- bf16 HMMA GEMM (validated R4) ----------------------------
#define GBK 32
#define ROWB 80
#define T_A  (128 * ROWB)
#define OFF_AH 0
#define OFF_AL (1 * T_A)
#define OFF_BH (2 * T_A)
#define OFF_BL (3 * T_A)
#define STAGE  (4 * T_A)
#define GEMM_SMEM (2 * STAGE)
#define NCH (HIDDEN / GBK)

template<int MODE>
__global__ __launch_bounds__(256) void gemm_hmma(
    const __nv_bfloat16* __restrict__ Ahp, const __nv_bfloat16* __restrict__ Alp,
    const __nv_bfloat16* __restrict__ Bhp, const __nv_bfloat16* __restrict__ Blp,
    float* __restrict__ out)
{
    extern __shared__ char smem[];
    const uint32_t sb = smem_u32(smem);
    const int tid = threadIdx.x;
    const int lane = tid & 31;
    const int warpId = tid >> 5;
    const int warpM = warpId >> 2;
    const int warpN = warpId & 3;
    const int rowBase = blockIdx.y * 128;
    const int colBase = blockIdx.x * 128;

    const int lr = lane & 15;
    const int lc = lane >> 4;

    float acc[4][4][4];
#pragma unroll
    for (int mt = 0; mt < 4; mt++)
#pragma unroll
        for (int nn = 0; nn < 4; nn++)
#pragma unroll
            for (int e = 0; e < 4; e++) acc[mt][nn][e] = 0.f;

    auto load_stage = [&](int buf, int chunk) {
        uint32_t base = sb + buf * STAGE;
        int kb = chunk * GBK;
#pragma unroll
        for (int i = 0; i < 2; i++) {
            int c4 = tid + 256 * i;
            int r = c4 >> 2, o = c4 & 3;
            uint32_t d = r * ROWB + o * 16;
            size_t sA = (size_t)(rowBase + r) * HIDDEN + kb + o * 8;
            size_t sB = (size_t)(colBase + r) * HIDDEN + kb + o * 8;
            cp16(base + OFF_AH + d, Ahp + sA);
            cp16(base + OFF_AL + d, Alp + sA);
            cp16(base + OFF_BH + d, Bhp + sB);
            cp16(base + OFF_BL + d, Blp + sB);
        }
        cp_commit();
    };

    load_stage(0, 0);
    load_stage(1, 1);

    for (int c = 0; c < NCH; c++) {
        if (c < NCH - 2) asm volatile("cp.async.wait_group 1;" ::: "memory");
        else             asm volatile("cp.async.wait_group 0;" ::: "memory");
        __syncthreads();

        uint32_t st = sb + (c & 1) * STAGE;
#pragma unroll
        for (int k16 = 0; k16 < 2; k16++) {
            const uint32_t kbyte = (k16 * 16 + lc * 8) * 2;
            uint32_t ah[4][4], al[4][4], bh[2][4], bl[2][4];
#pragma unroll
            for (int mt = 0; mt < 4; mt++) {
                uint32_t ro = (warpM * 64 + mt * 16 + lr) * ROWB + kbyte;
                ldsm4(ah[mt], st + OFF_AH + ro);
                ldsm4(al[mt], st + OFF_AL + ro);
            }
#pragma unroll
            for (int nt = 0; nt < 2; nt++) {
                uint32_t ro = (warpN * 32 + nt * 16 + lr) * ROWB + kbyte;
                ldsm4(bh[nt], st + OFF_BH + ro);
                ldsm4(bl[nt], st + OFF_BL + ro);
            }
#pragma unroll
            for (int mt = 0; mt < 4; mt++)
#pragma unroll
                for (int nn = 0; nn < 4; nn++) {
                    int nt = nn >> 1, hf = nn & 1;
                    mma_bf16(acc[mt][nn], ah[mt], bh[nt][hf], bh[nt][hf + 2]);
                    mma_bf16(acc[mt][nn], ah[mt], bl[nt][hf], bl[nt][hf + 2]);
                    mma_bf16(acc[mt][nn], al[mt], bh[nt][hf], bh[nt][hf + 2]);
                }
        }
        __syncthreads();
        if (c + 2 < NCH) load_stage(c & 1, c + 2);
    }

    const int er = lane >> 2, ec = (lane & 3) * 2;
#pragma unroll
    for (int mt = 0; mt < 4; mt++) {
#pragma unroll
        for (int nn = 0; nn < 4; nn++) {
            int col = colBase + warpN * 32 + nn * 8 + ec;
#pragma unroll
            for (int hf = 0; hf < 2; hf++) {
                int row = rowBase + warpM * 64 + mt * 16 + er + hf * 8;
                float v0 = acc[mt][nn][2 * hf];
                float v1 = acc[mt][nn][2 * hf + 1];
                if (MODE == 0) {
                    float2* p = (float2*)(out + (size_t)row * HIDDEN + col);
                    *p = make_float2(v0, v1);
                } else {
                    int b = row >> 11, s = row & (SEQ - 1);
                    int h = col >> 7, d = col & (HD - 1);
                    float2* p = (float2*)(out + (((size_t)b * NH + h) * SEQ + s) * HD + d);
                    *p = make_float2(v0, v1);
                }
            }
        }
    }
}

// ---------------- HMMA flash attention --------------------------------------
#define ROWP 272
#define KTILE (64 * ROWP)
#define QBYTES (128 * ROWP)
#define STG (4 * KTILE)
#define ATTN_SMEM (2 * QBYTES + 2 * STG)   // 208896 B

__global__ __launch_bounds__(256, 1) void attn_tc(
    const __nv_bfloat16* __restrict__ qh, const __nv_bfloat16* __restrict__ ql,
    const __nv_bfloat16* __restrict__ kh, const __nv_bfloat16* __restrict__ kl,
    const __nv_bfloat16* __restrict__ vh, const __nv_bfloat16* __restrict__ vl,
    __nv_bfloat16* __restrict__ outh, __nv_bfloat16* __restrict__ outl)
{
    extern __shared__ char sm[];
    const uint32_t sb = smem_u32(sm);
    const int tid = threadIdx.x;
    const int lane = tid & 31;
    const int w = tid >> 5;
    const int qt = blockIdx.x;
    const int bh = blockIdx.y;
    const size_t headOff = (size_t)bh * SEQ * HD;

    const uint32_t qsh = sb, qsl = sb + QBYTES;
    const uint32_t kvb0 = sb + 2 * QBYTES;

    // Q tile load
    {
        const __nv_bfloat16* qhp = qh + headOff + (size_t)qt * 128 * HD;
        const __nv_bfloat16* qlp = ql + headOff + (size_t)qt * 128 * HD;
#pragma unroll
        for (int i = 0; i < 8; i++) {
            int idx = tid + 256 * i;
            int r = idx >> 4, o = idx & 15;
            uint32_t d = r * ROWP + o * 16;
            size_t s = (size_t)r * HD + o * 8;
            cp16(qsh + d, qhp + s);
            cp16(qsl + d, qlp + s);
        }
        cp_commit();
    }

#define LOAD_KV(buf, t) do {                                                   \
        uint32_t base = kvb0 + (buf) * STG;                                    \
        size_t rb = headOff + (size_t)(t) * 64 * HD;                           \
        _Pragma("unroll")                                                      \
        for (int i = 0; i < 4; i++) {                                          \
            int idx = tid + 256 * i;                                           \
            int r = idx >> 4, o = idx & 15;                                    \
            uint32_t d = r * ROWP + o * 16;                                    \
            size_t s = rb + (size_t)r * HD + o * 8;                            \
            cp16(base + d,             kh + s);                                \
            cp16(base + KTILE + d,     kl + s);                                \
            cp16(base + 2 * KTILE + d, vh + s);                                \
            cp16(base + 3 * KTILE + d, vl + s);                                \
        }                                                                      \
        cp_commit();                                                           \
    } while (0)

    LOAD_KV(0, 0);
    LOAD_KV(1, 1);

    const int wq0 = w * 16;
    const uint32_t qoff = (uint32_t)(wq0 + (lane & 15)) * ROWP + ((lane >> 4) << 4);
    const uint32_t krow = (lane & 7) + ((lane >> 4) << 3);
    const uint32_t kcb  = ((lane >> 3) & 1) << 4;
    const uint32_t vrow = (lane & 7) + (((lane >> 3) & 1) << 3);
    const uint32_t vcb  = (lane >> 4) << 4;

    float m0 = -1e30f, m1 = -1e30f, l0 = 0.f, l1 = 0.f;
    float o[16][4];
#pragma unroll
    for (int t = 0; t < 16; t++)
#pragma unroll
        for (int e = 0; e < 4; e++) o[t][e] = 0.f;

    const int NT = SEQ / 64;
    for (int t = 0; t < NT; t++) {
        if (t < NT - 2) asm volatile("cp.async.wait_group 1;" ::: "memory");
        else            asm volatile("cp.async.wait_group 0;" ::: "memory");
        __syncthreads();

        const uint32_t kb = kvb0 + (t & 1) * STG;

        float sc[8][4];
#pragma unroll
        for (int tt = 0; tt < 8; tt++)
#pragma unroll
            for (int e = 0; e < 4; e++) sc[tt][e] = 0.f;

#pragma unroll
        for (int kg = 0; kg < 8; kg++) {
            uint32_t aqh[4], aql4[4];
            ldsm4(aqh,  qsh + qoff + kg * 32);
            ldsm4(aql4, qsl + qoff + kg * 32);
#pragma unroll
            for (int ng = 0; ng < 4; ng++) {
                uint32_t kh4[4], kl4[4];
                uint32_t ka = kb + (ng * 16 + krow) * ROWP + kcb + kg * 32;
                ldsm4(kh4, ka);
                ldsm4(kl4, ka + KTILE);
                mma_bf16(sc[2 * ng],     aqh,  kh4[0], kh4[1]);
                mma_bf16(sc[2 * ng + 1], aqh,  kh4[2], kh4[3]);
                mma_bf16(sc[2 * ng],     aqh,  kl4[0], kl4[1]);
                mma_bf16(sc[2 * ng + 1], aqh,  kl4[2], kl4[3]);
                mma_bf16(sc[2 * ng],     aql4, kh4[0], kh4[1]);
                mma_bf16(sc[2 * ng + 1], aql4, kh4[2], kh4[3]);
            }
        }

        float mx0 = -1e30f, mx1 = -1e30f;
#pragma unroll
        for (int tt = 0; tt < 8; tt++) {
            mx0 = fmaxf(mx0, fmaxf(sc[tt][0], sc[tt][1]));
            mx1 = fmaxf(mx1, fmaxf(sc[tt][2], sc[tt][3]));
        }
        mx0 = fmaxf(mx0, __shfl_xor_sync(0xffffffffu, mx0, 1));
        mx0 = fmaxf(mx0, __shfl_xor_sync(0xffffffffu, mx0, 2));
        mx1 = fmaxf(mx1, __shfl_xor_sync(0xffffffffu, mx1, 1));
        mx1 = fmaxf(mx1, __shfl_xor_sync(0xffffffffu, mx1, 2));

        float nm0 = fmaxf(m0, mx0), nm1 = fmaxf(m1, mx1);
        float c0 = exp2p(m0 - nm0), c1 = exp2p(m1 - nm1);
        m0 = nm0; m1 = nm1;

        uint32_t pah[4][4], pal[4][4];
        float rs0 = 0.f, rs1 = 0.f;
#pragma unroll
        for (int tt = 0; tt < 8; tt++) {
            float p0 = exp2p(sc[tt][0] - m0);
            float p1 = exp2p(sc[tt][1] - m0);
            float p2 = exp2p(sc[tt][2] - m1);
            float p3 = exp2p(sc[tt][3] - m1);
            rs0 += p0 + p1;
            rs1 += p2 + p3;
            int g = tt >> 1, ri = (tt & 1) * 2;
            uint32_t h01 = packbf(p0, p1);
            uint32_t h23 = packbf(p2, p3);
            pah[g][ri]     = h01;
            pah[g][ri + 1] = h23;
            float q0 = p0 - __int_as_float(h01 << 16);
            float q1 = p1 - __int_as_float(h01 & 0xffff0000u);
            float q2 = p2 - __int_as_float(h23 << 16);
            float q3 = p3 - __int_as_float(h23 & 0xffff0000u);
            pal[g][ri]     = packbf(q0, q1);
            pal[g][ri + 1] = packbf(q2, q3);
        }
        rs0 += __shfl_xor_sync(0xffffffffu, rs0, 1);
        rs0 += __shfl_xor_sync(0xffffffffu, rs0, 2);
        rs1 += __shfl_xor_sync(0xffffffffu, rs1, 1);
        rs1 += __shfl_xor_sync(0xffffffffu, rs1, 2);
        l0 = l0 * c0 + rs0;
        l1 = l1 * c1 + rs1;

#pragma unroll
        for (int tt = 0; tt < 16; tt++) {
            o[tt][0] *= c0; o[tt][1] *= c0;
            o[tt][2] *= c1; o[tt][3] *= c1;
        }

#pragma unroll
        for (int g = 0; g < 4; g++) {
#pragma unroll
            for (int dg = 0; dg < 8; dg++) {
                uint32_t v4h[4], v4l[4];
                uint32_t va = kb + 2 * KTILE + (g * 16 + vrow) * ROWP + vcb + dg * 32;
                ldsm4t(v4h, va);
                ldsm4t(v4l, va + KTILE);
                mma_bf16(o[2 * dg],     pah[g], v4h[0], v4h[1]);
                mma_bf16(o[2 * dg + 1], pah[g], v4h[2], v4h[3]);
                mma_bf16(o[2 * dg],     pah[g], v4l[0], v4l[1]);
                mma_bf16(o[2 * dg + 1], pah[g], v4l[2], v4l[3]);
                mma_bf16(o[2 * dg],     pal[g], v4h[0], v4h[1]);
                mma_bf16(o[2 * dg + 1], pal[g], v4h[2], v4h[3]);
            }
        }
        __syncthreads();
        if (t + 2 < NT) LOAD_KV(t & 1, t + 2);
    }
#undef LOAD_KV

    float il0 = 1.0f / l0, il1 = 1.0f / l1;
    int b = bh >> 4, h = bh & 15;
    int s0 = qt * 128 + wq0 + (lane >> 2);
    int s1 = s0 + 8;
    size_t row0 = ((size_t)b * SEQ + s0) * HIDDEN + h * HD;
    size_t row1 = ((size_t)b * SEQ + s1) * HIDDEN + h * HD;
    int dc = (lane & 3) * 2;
#pragma unroll
    for (int tt = 0; tt < 16; tt++) {
        int d = tt * 8 + dc;
        float f0 = o[tt][0] * il0, f1 = o[tt][1] * il0;
        float f2 = o[tt][2] * il1, f3 = o[tt][3] * il1;
        uint32_t h01 = packbf(f0, f1);
        uint32_t h23 = packbf(f2, f3);
        *(uint32_t*)(outh + row0 + d) = h01;
        *(uint32_t*)(outh + row1 + d) = h23;
        float q0 = f0 - __int_as_float(h01 << 16);
        float q1 = f1 - __int_as_float(h01 & 0xffff0000u);
        float q2 = f2 - __int_as_float(h23 << 16);
        float q3 = f3 - __int_as_float(h23 & 0xffff0000u);
        *(uint32_t*)(outl + row0 + d) = packbf(q0, q1);
        *(uint32_t*)(outl + row1 + d) = packbf(q2, q3);
    }
}

// ---------------------------------------------------------------------------
extern "C" void kernel_launch(void* const* d_in, const int* in_sizes, int n_in,
                              void* d_out, int out_size)
{
    const float* hidden = (const float*)d_in[0];
    const int*   posids = (const int*)d_in[1];
    const float* wk_in[4] = { (const float*)d_in[2], (const float*)d_in[3],
                              (const float*)d_in[4], (const float*)d_in[5] };
    float* out = (float*)d_out;

    float *q, *k, *v;
    __nv_bfloat16 *ah, *al, *wh, *wl, *qhp, *qlp, *khp, *klp, *vhp, *vlp;
    cudaGetSymbolAddress((void**)&q, g_q);
    cudaGetSymbolAddress((void**)&k, g_k);
    cudaGetSymbolAddress((void**)&v, g_v);
    cudaGetSymbolAddress((void**)&ah, g_ah);
    cudaGetSymbolAddress((void**)&al, g_al);
    cudaGetSymbolAddress((void**)&wh, g_wh);
    cudaGetSymbolAddress((void**)&wl, g_wl);
    cudaGetSymbolAddress((void**)&qhp, g_qh);
    cudaGetSymbolAddress((void**)&qlp, g_ql);
    cudaGetSymbolAddress((void**)&khp, g_kh);
    cudaGetSymbolAddress((void**)&klp, g_kl);
    cudaGetSymbolAddress((void**)&vhp, g_vh);
    cudaGetSymbolAddress((void**)&vlp, g_vl);
    const size_t wstep = (size_t)HIDDEN * HIDDEN;

    cudaFuncSetAttribute(gemm_hmma<0>, cudaFuncAttributeMaxDynamicSharedMemorySize, GEMM_SMEM);
    cudaFuncSetAttribute(gemm_hmma<1>, cudaFuncAttributeMaxDynamicSharedMemorySize, GEMM_SMEM);
    cudaFuncSetAttribute(attn_tc, cudaFuncAttributeMaxDynamicSharedMemorySize, ATTN_SMEM);

    pack_hl<<<(MROWS * HIDDEN) / 1024, 256>>>(hidden, ah, al);
    dim3 wg(HIDDEN / 32, HIDDEN / 32);
    for (int i = 0; i < 4; i++)
        pack_wT<<<wg, dim3(32, 8)>>>(wk_in[i], wh + i * wstep, wl + i * wstep);

    dim3 gg(HIDDEN / 128, MROWS / 128);

    gemm_hmma<1><<<gg, 256, GEMM_SMEM>>>(ah, al, wh + 0 * wstep, wl + 0 * wstep, q);
    gemm_hmma<1><<<gg, 256, GEMM_SMEM>>>(ah, al, wh + 1 * wstep, wl + 1 * wstep, k);
    gemm_hmma<1><<<gg, 256, GEMM_SMEM>>>(ah, al, wh + 2 * wstep, wl + 2 * wstep, v);

    dim3 rg(SEQ / 4, BATCH * NH);
    rope_pack<<<rg, 256>>>(q, posids, qhp, qlp, QSC);
    rope_pack<<<rg, 256>>>(k, posids, khp, klp, 1.0f);
    pack_hl<<<((size_t)BATCH * NH * SEQ * HD) / 1024, 256>>>(v, vhp, vlp);

    dim3 ag(SEQ / 128, BATCH * NH);
    attn_tc<<<ag, 256, ATTN_SMEM>>>(qhp, qlp, khp, klp, vhp, vlp, ah, al);

    gemm_hmma<0><<<gg, 256, GEMM_SMEM>>>(ah, al, wh + 3 * wstep, wl + 3 * wstep, out);
}

// round 6
// speedup vs baseline: 3.4227x; 1.1784x over previous
#include <cuda_runtime.h>
#include <cuda_fp16.h>
#include <math.h>
#include <stdint.h>

#define HIDDEN 2048
#define NH 16
#define HD 128
#define BATCH 2
#define SEQ 2048
#define MROWS (BATCH*SEQ)   // 4096

// 1/sqrt(128) * log2(e)
#define QSC 0.1275174277f

// ---------------- scratch (device globals) ----------------------------------
__device__ float g_q[(size_t)BATCH*NH*SEQ*HD];     // (b,h,s,d) fp32
__device__ float g_k[(size_t)BATCH*NH*SEQ*HD];

__device__ __half g_ah[(size_t)MROWS*HIDDEN];      // A hi (hidden / attn out)
__device__ __half g_al[(size_t)MROWS*HIDDEN];      // A lo
__device__ __half g_whi[4][(size_t)HIDDEN*HIDDEN]; // W^T hi (q,k,v,o)
__device__ __half g_wlo[2][(size_t)HIDDEN*HIDDEN]; // W^T lo (q,k only)

__device__ __half g_qh[(size_t)BATCH*NH*SEQ*HD];   // roped+scaled Q hi/lo
__device__ __half g_ql[(size_t)BATCH*NH*SEQ*HD];
__device__ __half g_kh[(size_t)BATCH*NH*SEQ*HD];   // roped K hi/lo
__device__ __half g_kl[(size_t)BATCH*NH*SEQ*HD];
__device__ __half g_vh[(size_t)BATCH*NH*SEQ*HD];   // V single fp16

// ---------------- PTX helpers ------------------------------------------------
__device__ __forceinline__ uint32_t smem_u32(const void* p) {
    uint32_t a;
    asm("{ .reg .u64 t; cvta.to.shared.u64 t, %1; cvt.u32.u64 %0, t; }" : "=r"(a) : "l"(p));
    return a;
}
__device__ __forceinline__ void cp16(uint32_t dst, const void* src) {
    asm volatile("cp.async.cg.shared.global [%0], [%1], 16;" :: "r"(dst), "l"(src));
}
__device__ __forceinline__ void cp_commit() { asm volatile("cp.async.commit_group;"); }

__device__ __forceinline__ void ldsm4(uint32_t* r, uint32_t addr) {
    asm volatile("ldmatrix.sync.aligned.m8n8.x4.shared.b16 {%0,%1,%2,%3}, [%4];"
                 : "=r"(r[0]), "=r"(r[1]), "=r"(r[2]), "=r"(r[3]) : "r"(addr));
}
__device__ __forceinline__ void ldsm4t(uint32_t* r, uint32_t addr) {
    asm volatile("ldmatrix.sync.aligned.m8n8.x4.trans.shared.b16 {%0,%1,%2,%3}, [%4];"
                 : "=r"(r[0]), "=r"(r[1]), "=r"(r[2]), "=r"(r[3]) : "r"(addr));
}
__device__ __forceinline__ void mma_f16(float* c, const uint32_t* a, uint32_t b0, uint32_t b1) {
    asm volatile(
        "mma.sync.aligned.m16n8k16.row.col.f32.f16.f16.f32 "
        "{%0,%1,%2,%3}, {%4,%5,%6,%7}, {%8,%9}, {%0,%1,%2,%3};"
        : "+f"(c[0]), "+f"(c[1]), "+f"(c[2]), "+f"(c[3])
        : "r"(a[0]), "r"(a[1]), "r"(a[2]), "r"(a[3]), "r"(b0), "r"(b1));
}
// pack (lo, hi) floats -> f16x2 (first PTX source -> upper half)
__device__ __forceinline__ uint32_t packh2(float lo, float hi) {
    uint32_t r;
    asm("cvt.rn.f16x2.f32 %0, %1, %2;" : "=r"(r) : "f"(hi), "f"(lo));
    return r;
}
// fast 2^x on FMA pipe, x <= 0
__device__ __forceinline__ float exp2p(float x) {
    x = fmaxf(x, -120.0f);
    float n = rintf(x);
    float f = x - n;
    float p = fmaf(f, 0.0013333558f, 0.0096181291f);
    p = fmaf(f, p, 0.0555041087f);
    p = fmaf(f, p, 0.2402265070f);
    p = fmaf(f, p, 0.6931471806f);
    p = fmaf(f, p, 1.0f);
    return __int_as_float(__float_as_int(p) + ((int)n << 23));
}

// ---------------- pack kernels ----------------------------------------------
__global__ __launch_bounds__(256) void pack_hl(const float* __restrict__ src,
                                               __half* __restrict__ hi,
                                               __half* __restrict__ lo)
{
    size_t i = ((size_t)blockIdx.x * 256 + threadIdx.x) * 4;
    float4 v = *(const float4*)(src + i);
    __half h[4], l[4];
    const float* f = (const float*)&v;
#pragma unroll
    for (int e = 0; e < 4; e++) {
        h[e] = __float2half_rn(f[e]);
        l[e] = __float2half_rn(f[e] - __half2float(h[e]));
    }
    *(uint2*)(hi + i) = *(uint2*)h;
    *(uint2*)(lo + i) = *(uint2*)l;
}

// W [K][N] -> Wt hi/lo [N][K]   (SPLIT=1: also write lo)
template<int SPLIT>
__global__ __launch_bounds__(256) void pack_wT(const float* __restrict__ W,
                                               __half* __restrict__ th,
                                               __half* __restrict__ tl)
{
    __shared__ float t[32][33];
    int n0 = blockIdx.x * 32, k0 = blockIdx.y * 32;
    int tx = threadIdx.x, ty = threadIdx.y;   // (32, 8)
#pragma unroll
    for (int j = 0; j < 4; j++)
        t[ty + 8 * j][tx] = W[(size_t)(k0 + ty + 8 * j) * HIDDEN + n0 + tx];
    __syncthreads();
#pragma unroll
    for (int j = 0; j < 4; j++) {
        float x = t[tx][ty + 8 * j];
        __half h = __float2half_rn(x);
        size_t o = (size_t)(n0 + ty + 8 * j) * HIDDEN + k0 + tx;
        th[o] = h;
        if (SPLIT) tl[o] = __float2half_rn(x - __half2float(h));
    }
}

__global__ __launch_bounds__(256) void rope_pack(const float* __restrict__ src,
                                                 const int* __restrict__ pos_ids,
                                                 __half* __restrict__ hi,
                                                 __half* __restrict__ lo,
                                                 float scale)
{
    int lane = threadIdx.x & 63;
    int rsub = threadIdx.x >> 6;
    int s = blockIdx.x * 4 + rsub;
    int bh = blockIdx.y;
    int pos = pos_ids[s];

    float t = powf(10000.0f, (float)(2 * lane) * (1.0f / 128.0f));
    float ang = (float)pos * (1.0f / t);
    float sn, cs;
    sincosf(ang, &sn, &cs);

    const float* p = src + ((size_t)bh * SEQ + s) * HD;
    float x1 = p[lane];
    float x2 = p[lane + 64];
    float y1 = (x1 * cs - x2 * sn) * scale;
    float y2 = (x2 * cs + x1 * sn) * scale;

    size_t o = ((size_t)bh * SEQ + s) * HD;
    __half h1 = __float2half_rn(y1);
    __half h2 = __float2half_rn(y2);
    hi[o + lane]      = h1;
    hi[o + lane + 64] = h2;
    lo[o + lane]      = __float2half_rn(y1 - __half2float(h1));
    lo[o + lane + 64] = __float2half_rn(y2 - __half2float(h2));
}

// ---------------- fp16 HMMA GEMM --------------------------------------------
// C[4096,2048] = A * W,  B pre-transposed (Wt[n][k]).
// TERMS=3: C = AhBh + AhBl + AlBh (score path).
// TERMS=2: C = AhBh + AlBh       (B single fp16; linear path).
// MODE: 0 fp32 row-major; 1 fp32 scatter (b,h,s,d); 2 fp16 scatter.
#define GBK 32
#define ROWB 80
#define T_A  (128 * ROWB)
#define OFF_AH 0
#define OFF_AL (1 * T_A)
#define OFF_BH (2 * T_A)
#define OFF_BL (3 * T_A)
#define NCH (HIDDEN / GBK)
#define GEMM_SMEM3 (2 * 4 * T_A)   // 81920
#define GEMM_SMEM2 (2 * 3 * T_A)   // 61440

template<int MODE, int TERMS>
__global__ __launch_bounds__(256) void gemm_hmma(
    const __half* __restrict__ Ahp, const __half* __restrict__ Alp,
    const __half* __restrict__ Bhp, const __half* __restrict__ Blp,
    void* __restrict__ outv)
{
    constexpr int SSTR = (TERMS == 3 ? 4 : 3) * T_A;
    extern __shared__ char smem[];
    const uint32_t sb = smem_u32(smem);
    const int tid = threadIdx.x;
    const int lane = tid & 31;
    const int warpId = tid >> 5;
    const int warpM = warpId >> 2;
    const int warpN = warpId & 3;
    const int rowBase = blockIdx.y * 128;
    const int colBase = blockIdx.x * 128;

    const int lr = lane & 15;
    const int lc = lane >> 4;

    float acc[4][4][4];
#pragma unroll
    for (int mt = 0; mt < 4; mt++)
#pragma unroll
        for (int nn = 0; nn < 4; nn++)
#pragma unroll
            for (int e = 0; e < 4; e++) acc[mt][nn][e] = 0.f;

    auto load_stage = [&](int buf, int chunk) {
        uint32_t base = sb + buf * SSTR;
        int kb = chunk * GBK;
#pragma unroll
        for (int i = 0; i < 2; i++) {
            int c4 = tid + 256 * i;
            int r = c4 >> 2, o = c4 & 3;
            uint32_t d = r * ROWB + o * 16;
            size_t sA = (size_t)(rowBase + r) * HIDDEN + kb + o * 8;
            size_t sB = (size_t)(colBase + r) * HIDDEN + kb + o * 8;
            cp16(base + OFF_AH + d, Ahp + sA);
            cp16(base + OFF_AL + d, Alp + sA);
            cp16(base + OFF_BH + d, Bhp + sB);
            if (TERMS == 3) cp16(base + OFF_BL + d, Blp + sB);
        }
        cp_commit();
    };

    load_stage(0, 0);
    load_stage(1, 1);

    for (int c = 0; c < NCH; c++) {
        if (c < NCH - 2) asm volatile("cp.async.wait_group 1;" ::: "memory");
        else             asm volatile("cp.async.wait_group 0;" ::: "memory");
        __syncthreads();

        uint32_t st = sb + (c & 1) * SSTR;
#pragma unroll
        for (int k16 = 0; k16 < 2; k16++) {
            const uint32_t kbyte = (k16 * 16 + lc * 8) * 2;
            uint32_t ah[4][4], al[4][4], bh[2][4], bl[2][4];
#pragma unroll
            for (int mt = 0; mt < 4; mt++) {
                uint32_t ro = (warpM * 64 + mt * 16 + lr) * ROWB + kbyte;
                ldsm4(ah[mt], st + OFF_AH + ro);
                ldsm4(al[mt], st + OFF_AL + ro);
            }
#pragma unroll
            for (int nt = 0; nt < 2; nt++) {
                uint32_t ro = (warpN * 32 + nt * 16 + lr) * ROWB + kbyte;
                ldsm4(bh[nt], st + OFF_BH + ro);
                if (TERMS == 3) ldsm4(bl[nt], st + OFF_BL + ro);
            }
#pragma unroll
            for (int mt = 0; mt < 4; mt++)
#pragma unroll
                for (int nn = 0; nn < 4; nn++) {
                    int nt = nn >> 1, hf = nn & 1;
                    mma_f16(acc[mt][nn], ah[mt], bh[nt][hf], bh[nt][hf + 2]);
                    if (TERMS == 3)
                        mma_f16(acc[mt][nn], ah[mt], bl[nt][hf], bl[nt][hf + 2]);
                    mma_f16(acc[mt][nn], al[mt], bh[nt][hf], bh[nt][hf + 2]);
                }
        }
        __syncthreads();
        if (c + 2 < NCH) load_stage(c & 1, c + 2);
    }

    const int er = lane >> 2, ec = (lane & 3) * 2;
#pragma unroll
    for (int mt = 0; mt < 4; mt++) {
#pragma unroll
        for (int nn = 0; nn < 4; nn++) {
            int col = colBase + warpN * 32 + nn * 8 + ec;
#pragma unroll
            for (int hf = 0; hf < 2; hf++) {
                int row = rowBase + warpM * 64 + mt * 16 + er + hf * 8;
                float v0 = acc[mt][nn][2 * hf];
                float v1 = acc[mt][nn][2 * hf + 1];
                if (MODE == 0) {
                    *(float2*)((float*)outv + (size_t)row * HIDDEN + col) = make_float2(v0, v1);
                } else if (MODE == 1) {
                    int b = row >> 11, s = row & (SEQ - 1);
                    int h = col >> 7, d = col & (HD - 1);
                    *(float2*)((float*)outv + (((size_t)b * NH + h) * SEQ + s) * HD + d) =
                        make_float2(v0, v1);
                } else {
                    int b = row >> 11, s = row & (SEQ - 1);
                    int h = col >> 7, d = col & (HD - 1);
                    *(uint32_t*)((__half*)outv + (((size_t)b * NH + h) * SEQ + s) * HD + d) =
                        packh2(v0, v1);
                }
            }
        }
    }
}

// ---------------- fp16 HMMA flash attention ----------------------------------
// QK^T: 3 products; PV: 2 products (V single fp16).
#define ROWP 272
#define KTILE (64 * ROWP)
#define QBYTES (128 * ROWP)
#define STG (3 * KTILE)                      // Kh, Kl, V
#define ATTN_SMEM (2 * QBYTES + 2 * STG)     // 174080

__global__ __launch_bounds__(256, 1) void attn_tc(
    const __half* __restrict__ qh, const __half* __restrict__ ql,
    const __half* __restrict__ kh, const __half* __restrict__ kl,
    const __half* __restrict__ vh,
    __half* __restrict__ outh, __half* __restrict__ outl)
{
    extern __shared__ char sm[];
    const uint32_t sb = smem_u32(sm);
    const int tid = threadIdx.x;
    const int lane = tid & 31;
    const int w = tid >> 5;
    const int qt = blockIdx.x;
    const int bh = blockIdx.y;
    const size_t headOff = (size_t)bh * SEQ * HD;

    const uint32_t qsh = sb, qsl = sb + QBYTES;
    const uint32_t kvb0 = sb + 2 * QBYTES;

    {
        const __half* qhp = qh + headOff + (size_t)qt * 128 * HD;
        const __half* qlp = ql + headOff + (size_t)qt * 128 * HD;
#pragma unroll
        for (int i = 0; i < 8; i++) {
            int idx = tid + 256 * i;
            int r = idx >> 4, o = idx & 15;
            uint32_t d = r * ROWP + o * 16;
            size_t s = (size_t)r * HD + o * 8;
            cp16(qsh + d, qhp + s);
            cp16(qsl + d, qlp + s);
        }
        cp_commit();
    }

#define LOAD_KV(buf, t) do {                                                   \
        uint32_t base = kvb0 + (buf) * STG;                                    \
        size_t rb = headOff + (size_t)(t) * 64 * HD;                           \
        _Pragma("unroll")                                                      \
        for (int i = 0; i < 4; i++) {                                          \
            int idx = tid + 256 * i;                                           \
            int r = idx >> 4, o = idx & 15;                                    \
            uint32_t d = r * ROWP + o * 16;                                    \
            size_t s = rb + (size_t)r * HD + o * 8;                            \
            cp16(base + d,             kh + s);                                \
            cp16(base + KTILE + d,     kl + s);                                \
            cp16(base + 2 * KTILE + d, vh + s);                                \
        }                                                                      \
        cp_commit();                                                           \
    } while (0)

    LOAD_KV(0, 0);
    LOAD_KV(1, 1);

    const int wq0 = w * 16;
    const uint32_t qoff = (uint32_t)(wq0 + (lane & 15)) * ROWP + ((lane >> 4) << 4);
    const uint32_t krow = (lane & 7) + ((lane >> 4) << 3);
    const uint32_t kcb  = ((lane >> 3) & 1) << 4;
    const uint32_t vrow = (lane & 7) + (((lane >> 3) & 1) << 3);
    const uint32_t vcb  = (lane >> 4) << 4;

    float m0 = -1e30f, m1 = -1e30f, l0 = 0.f, l1 = 0.f;
    float o[16][4];
#pragma unroll
    for (int t = 0; t < 16; t++)
#pragma unroll
        for (int e = 0; e < 4; e++) o[t][e] = 0.f;

    const int NT = SEQ / 64;
    for (int t = 0; t < NT; t++) {
        if (t < NT - 2) asm volatile("cp.async.wait_group 1;" ::: "memory");
        else            asm volatile("cp.async.wait_group 0;" ::: "memory");
        __syncthreads();

        const uint32_t kb = kvb0 + (t & 1) * STG;

        float sc[8][4];
#pragma unroll
        for (int tt = 0; tt < 8; tt++)
#pragma unroll
            for (int e = 0; e < 4; e++) sc[tt][e] = 0.f;

#pragma unroll
        for (int kg = 0; kg < 8; kg++) {
            uint32_t aqh[4], aql4[4];
            ldsm4(aqh,  qsh + qoff + kg * 32);
            ldsm4(aql4, qsl + qoff + kg * 32);
#pragma unroll
            for (int ng = 0; ng < 4; ng++) {
                uint32_t kh4[4], kl4[4];
                uint32_t ka = kb + (ng * 16 + krow) * ROWP + kcb + kg * 32;
                ldsm4(kh4, ka);
                ldsm4(kl4, ka + KTILE);
                mma_f16(sc[2 * ng],     aqh,  kh4[0], kh4[1]);
                mma_f16(sc[2 * ng + 1], aqh,  kh4[2], kh4[3]);
                mma_f16(sc[2 * ng],     aqh,  kl4[0], kl4[1]);
                mma_f16(sc[2 * ng + 1], aqh,  kl4[2], kl4[3]);
                mma_f16(sc[2 * ng],     aql4, kh4[0], kh4[1]);
                mma_f16(sc[2 * ng + 1], aql4, kh4[2], kh4[3]);
            }
        }

        float mx0 = -1e30f, mx1 = -1e30f;
#pragma unroll
        for (int tt = 0; tt < 8; tt++) {
            mx0 = fmaxf(mx0, fmaxf(sc[tt][0], sc[tt][1]));
            mx1 = fmaxf(mx1, fmaxf(sc[tt][2], sc[tt][3]));
        }
        mx0 = fmaxf(mx0, __shfl_xor_sync(0xffffffffu, mx0, 1));
        mx0 = fmaxf(mx0, __shfl_xor_sync(0xffffffffu, mx0, 2));
        mx1 = fmaxf(mx1, __shfl_xor_sync(0xffffffffu, mx1, 1));
        mx1 = fmaxf(mx1, __shfl_xor_sync(0xffffffffu, mx1, 2));

        float nm0 = fmaxf(m0, mx0), nm1 = fmaxf(m1, mx1);
        float c0 = exp2p(m0 - nm0), c1 = exp2p(m1 - nm1);
        m0 = nm0; m1 = nm1;

        uint32_t pah[4][4], pal[4][4];
        float rs0 = 0.f, rs1 = 0.f;
#pragma unroll
        for (int tt = 0; tt < 8; tt++) {
            float p0 = exp2p(sc[tt][0] - m0);
            float p1 = exp2p(sc[tt][1] - m0);
            float p2 = exp2p(sc[tt][2] - m1);
            float p3 = exp2p(sc[tt][3] - m1);
            rs0 += p0 + p1;
            rs1 += p2 + p3;
            int g = tt >> 1, ri = (tt & 1) * 2;
            uint32_t h01 = packh2(p0, p1);
            uint32_t h23 = packh2(p2, p3);
            pah[g][ri]     = h01;
            pah[g][ri + 1] = h23;
            __half2 hv01 = *(__half2*)&h01;
            __half2 hv23 = *(__half2*)&h23;
            pal[g][ri]     = packh2(p0 - __low2float(hv01), p1 - __high2float(hv01));
            pal[g][ri + 1] = packh2(p2 - __low2float(hv23), p3 - __high2float(hv23));
        }
        rs0 += __shfl_xor_sync(0xffffffffu, rs0, 1);
        rs0 += __shfl_xor_sync(0xffffffffu, rs0, 2);
        rs1 += __shfl_xor_sync(0xffffffffu, rs1, 1);
        rs1 += __shfl_xor_sync(0xffffffffu, rs1, 2);
        l0 = l0 * c0 + rs0;
        l1 = l1 * c1 + rs1;

#pragma unroll
        for (int tt = 0; tt < 16; tt++) {
            o[tt][0] *= c0; o[tt][1] *= c0;
            o[tt][2] *= c1; o[tt][3] *= c1;
        }

#pragma unroll
        for (int g = 0; g < 4; g++) {
#pragma unroll
            for (int dg = 0; dg < 8; dg++) {
                uint32_t v4[4];
                uint32_t va = kb + 2 * KTILE + (g * 16 + vrow) * ROWP + vcb + dg * 32;
                ldsm4t(v4, va);
                mma_f16(o[2 * dg],     pah[g], v4[0], v4[1]);
                mma_f16(o[2 * dg + 1], pah[g], v4[2], v4[3]);
                mma_f16(o[2 * dg],     pal[g], v4[0], v4[1]);
                mma_f16(o[2 * dg + 1], pal[g], v4[2], v4[3]);
            }
        }
        __syncthreads();
        if (t + 2 < NT) LOAD_KV(t & 1, t + 2);
    }
#undef LOAD_KV

    float il0 = 1.0f / l0, il1 = 1.0f / l1;
    int b = bh >> 4, h = bh & 15;
    int s0 = qt * 128 + wq0 + (lane >> 2);
    int s1 = s0 + 8;
    size_t row0 = ((size_t)b * SEQ + s0) * HIDDEN + h * HD;
    size_t row1 = ((size_t)b * SEQ + s1) * HIDDEN + h * HD;
    int dc = (lane & 3) * 2;
#pragma unroll
    for (int tt = 0; tt < 16; tt++) {
        int d = tt * 8 + dc;
        float f0 = o[tt][0] * il0, f1 = o[tt][1] * il0;
        float f2 = o[tt][2] * il1, f3 = o[tt][3] * il1;
        uint32_t h01 = packh2(f0, f1);
        uint32_t h23 = packh2(f2, f3);
        *(uint32_t*)(outh + row0 + d) = h01;
        *(uint32_t*)(outh + row1 + d) = h23;
        __half2 hv01 = *(__half2*)&h01;
        __half2 hv23 = *(__half2*)&h23;
        *(uint32_t*)(outl + row0 + d) = packh2(f0 - __low2float(hv01), f1 - __high2float(hv01));
        *(uint32_t*)(outl + row1 + d) = packh2(f2 - __low2float(hv23), f3 - __high2float(hv23));
    }
}

// ---------------------------------------------------------------------------
extern "C" void kernel_launch(void* const* d_in, const int* in_sizes, int n_in,
                              void* d_out, int out_size)
{
    const float* hidden = (const float*)d_in[0];
    const int*   posids = (const int*)d_in[1];
    const float* wq = (const float*)d_in[2];
    const float* wk = (const float*)d_in[3];
    const float* wv = (const float*)d_in[4];
    const float* wo = (const float*)d_in[5];
    float* out = (float*)d_out;

    float *q, *k;
    __half *ah, *al, *whi, *wlo, *qhp, *qlp, *khp, *klp, *vhp;
    cudaGetSymbolAddress((void**)&q, g_q);
    cudaGetSymbolAddress((void**)&k, g_k);
    cudaGetSymbolAddress((void**)&ah, g_ah);
    cudaGetSymbolAddress((void**)&al, g_al);
    cudaGetSymbolAddress((void**)&whi, g_whi);
    cudaGetSymbolAddress((void**)&wlo, g_wlo);
    cudaGetSymbolAddress((void**)&qhp, g_qh);
    cudaGetSymbolAddress((void**)&qlp, g_ql);
    cudaGetSymbolAddress((void**)&khp, g_kh);
    cudaGetSymbolAddress((void**)&klp, g_kl);
    cudaGetSymbolAddress((void**)&vhp, g_vh);
    const size_t wstep = (size_t)HIDDEN * HIDDEN;

    cudaFuncSetAttribute(gemm_hmma<1,3>, cudaFuncAttributeMaxDynamicSharedMemorySize, GEMM_SMEM3);
    cudaFuncSetAttribute(gemm_hmma<2,2>, cudaFuncAttributeMaxDynamicSharedMemorySize, GEMM_SMEM2);
    cudaFuncSetAttribute(gemm_hmma<0,2>, cudaFuncAttributeMaxDynamicSharedMemorySize, GEMM_SMEM2);
    cudaFuncSetAttribute(attn_tc, cudaFuncAttributeMaxDynamicSharedMemorySize, ATTN_SMEM);

    // packs
    pack_hl<<<(MROWS * HIDDEN) / 1024, 256>>>(hidden, ah, al);
    dim3 wg(HIDDEN / 32, HIDDEN / 32);
    pack_wT<1><<<wg, dim3(32, 8)>>>(wq, whi + 0 * wstep, wlo + 0 * wstep);
    pack_wT<1><<<wg, dim3(32, 8)>>>(wk, whi + 1 * wstep, wlo + 1 * wstep);
    pack_wT<0><<<wg, dim3(32, 8)>>>(wv, whi + 2 * wstep, nullptr);
    pack_wT<0><<<wg, dim3(32, 8)>>>(wo, whi + 3 * wstep, nullptr);

    dim3 gg(HIDDEN / 128, MROWS / 128);

    // projections: Q,K 3-term fp32 scatter; V 2-term fp16 scatter
    gemm_hmma<1,3><<<gg, 256, GEMM_SMEM3>>>(ah, al, whi + 0 * wstep, wlo + 0 * wstep, q);
    gemm_hmma<1,3><<<gg, 256, GEMM_SMEM3>>>(ah, al, whi + 1 * wstep, wlo + 1 * wstep, k);
    gemm_hmma<2,2><<<gg, 256, GEMM_SMEM2>>>(ah, al, whi + 2 * wstep, nullptr, vhp);

    // RoPE + fp16 hi/lo pack
    dim3 rg(SEQ / 4, BATCH * NH);
    rope_pack<<<rg, 256>>>(q, posids, qhp, qlp, QSC);
    rope_pack<<<rg, 256>>>(k, posids, khp, klp, 1.0f);

    // attention -> writes fp16 hi/lo into O-proj A buffers
    dim3 ag(SEQ / 128, BATCH * NH);
    attn_tc<<<ag, 256, ATTN_SMEM>>>(qhp, qlp, khp, klp, vhp, ah, al);

    // O projection (2-term, fp32 row-major out)
    gemm_hmma<0,2><<<gg, 256, GEMM_SMEM2>>>(ah, al, whi + 3 * wstep, nullptr, out);
}

// round 7
// speedup vs baseline: 4.0375x; 1.1796x over previous
#include <cuda_runtime.h>
#include <cuda_fp16.h>
#include <math.h>
#include <stdint.h>

#define HIDDEN 2048
#define NH 16
#define HD 128
#define BATCH 2
#define SEQ 2048
#define MROWS (BATCH*SEQ)   // 4096

// 1/sqrt(128) * log2(e)
#define QSC 0.1275174277f

// ---------------- scratch (device globals) ----------------------------------
__device__ float g_q[(size_t)BATCH*NH*SEQ*HD];     // (b,h,s,d) fp32
__device__ float g_k[(size_t)BATCH*NH*SEQ*HD];

__device__ __half g_ah[(size_t)MROWS*HIDDEN];      // A hi (hidden / attn out)
__device__ __half g_al[(size_t)MROWS*HIDDEN];      // A lo (hidden only)
__device__ __half g_whi[4][(size_t)HIDDEN*HIDDEN]; // W^T hi (q,k,v,o)
__device__ __half g_wlo[2][(size_t)HIDDEN*HIDDEN]; // W^T lo (q,k only)

__device__ __half g_qh[(size_t)BATCH*NH*SEQ*HD];   // roped+scaled Q hi/lo
__device__ __half g_ql[(size_t)BATCH*NH*SEQ*HD];
__device__ __half g_kh[(size_t)BATCH*NH*SEQ*HD];   // roped K hi/lo
__device__ __half g_kl[(size_t)BATCH*NH*SEQ*HD];
__device__ __half g_vh[(size_t)BATCH*NH*SEQ*HD];   // V single fp16

// ---------------- PTX helpers ------------------------------------------------
__device__ __forceinline__ uint32_t smem_u32(const void* p) {
    uint32_t a;
    asm("{ .reg .u64 t; cvta.to.shared.u64 t, %1; cvt.u32.u64 %0, t; }" : "=r"(a) : "l"(p));
    return a;
}
__device__ __forceinline__ void cp16(uint32_t dst, const void* src) {
    asm volatile("cp.async.cg.shared.global [%0], [%1], 16;" :: "r"(dst), "l"(src));
}
__device__ __forceinline__ void cp_commit() { asm volatile("cp.async.commit_group;"); }

__device__ __forceinline__ void ldsm4(uint32_t* r, uint32_t addr) {
    asm volatile("ldmatrix.sync.aligned.m8n8.x4.shared.b16 {%0,%1,%2,%3}, [%4];"
                 : "=r"(r[0]), "=r"(r[1]), "=r"(r[2]), "=r"(r[3]) : "r"(addr));
}
__device__ __forceinline__ void ldsm4t(uint32_t* r, uint32_t addr) {
    asm volatile("ldmatrix.sync.aligned.m8n8.x4.trans.shared.b16 {%0,%1,%2,%3}, [%4];"
                 : "=r"(r[0]), "=r"(r[1]), "=r"(r[2]), "=r"(r[3]) : "r"(addr));
}
__device__ __forceinline__ void mma_f16(float* c, const uint32_t* a, uint32_t b0, uint32_t b1) {
    asm volatile(
        "mma.sync.aligned.m16n8k16.row.col.f32.f16.f16.f32 "
        "{%0,%1,%2,%3}, {%4,%5,%6,%7}, {%8,%9}, {%0,%1,%2,%3};"
        : "+f"(c[0]), "+f"(c[1]), "+f"(c[2]), "+f"(c[3])
        : "r"(a[0]), "r"(a[1]), "r"(a[2]), "r"(a[3]), "r"(b0), "r"(b1));
}
__device__ __forceinline__ uint32_t packh2(float lo, float hi) {
    uint32_t r;
    asm("cvt.rn.f16x2.f32 %0, %1, %2;" : "=r"(r) : "f"(hi), "f"(lo));
    return r;
}
// fast 2^x on FMA pipe, x <= 0
__device__ __forceinline__ float exp2p(float x) {
    x = fmaxf(x, -120.0f);
    float n = rintf(x);
    float f = x - n;
    float p = fmaf(f, 0.0013333558f, 0.0096181291f);
    p = fmaf(f, p, 0.0555041087f);
    p = fmaf(f, p, 0.2402265070f);
    p = fmaf(f, p, 0.6931471806f);
    p = fmaf(f, p, 1.0f);
    return __int_as_float(__float_as_int(p) + ((int)n << 23));
}

// ---------------- pack kernels ----------------------------------------------
__global__ __launch_bounds__(256) void pack_hl(const float* __restrict__ src,
                                               __half* __restrict__ hi,
                                               __half* __restrict__ lo)
{
    size_t i = ((size_t)blockIdx.x * 256 + threadIdx.x) * 4;
    float4 v = *(const float4*)(src + i);
    __half h[4], l[4];
    const float* f = (const float*)&v;
#pragma unroll
    for (int e = 0; e < 4; e++) {
        h[e] = __float2half_rn(f[e]);
        l[e] = __float2half_rn(f[e] - __half2float(h[e]));
    }
    *(uint2*)(hi + i) = *(uint2*)h;
    *(uint2*)(lo + i) = *(uint2*)l;
}

template<int SPLIT>
__global__ __launch_bounds__(256) void pack_wT(const float* __restrict__ W,
                                               __half* __restrict__ th,
                                               __half* __restrict__ tl)
{
    __shared__ float t[32][33];
    int n0 = blockIdx.x * 32, k0 = blockIdx.y * 32;
    int tx = threadIdx.x, ty = threadIdx.y;   // (32, 8)
#pragma unroll
    for (int j = 0; j < 4; j++)
        t[ty + 8 * j][tx] = W[(size_t)(k0 + ty + 8 * j) * HIDDEN + n0 + tx];
    __syncthreads();
#pragma unroll
    for (int j = 0; j < 4; j++) {
        float x = t[tx][ty + 8 * j];
        __half h = __float2half_rn(x);
        size_t o = (size_t)(n0 + ty + 8 * j) * HIDDEN + k0 + tx;
        th[o] = h;
        if (SPLIT) tl[o] = __float2half_rn(x - __half2float(h));
    }
}

__global__ __launch_bounds__(256) void rope_pack(const float* __restrict__ src,
                                                 const int* __restrict__ pos_ids,
                                                 __half* __restrict__ hi,
                                                 __half* __restrict__ lo,
                                                 float scale)
{
    int lane = threadIdx.x & 63;
    int rsub = threadIdx.x >> 6;
    int s = blockIdx.x * 4 + rsub;
    int bh = blockIdx.y;
    int pos = pos_ids[s];

    float t = powf(10000.0f, (float)(2 * lane) * (1.0f / 128.0f));
    float ang = (float)pos * (1.0f / t);
    float sn, cs;
    sincosf(ang, &sn, &cs);

    const float* p = src + ((size_t)bh * SEQ + s) * HD;
    float x1 = p[lane];
    float x2 = p[lane + 64];
    float y1 = (x1 * cs - x2 * sn) * scale;
    float y2 = (x2 * cs + x1 * sn) * scale;

    size_t o = ((size_t)bh * SEQ + s) * HD;
    __half h1 = __float2half_rn(y1);
    __half h2 = __float2half_rn(y2);
    hi[o + lane]      = h1;
    hi[o + lane + 64] = h2;
    lo[o + lane]      = __float2half_rn(y1 - __half2float(h1));
    lo[o + lane + 64] = __float2half_rn(y2 - __half2float(h2));
}

// ---------------- fp16 HMMA GEMM --------------------------------------------
// C[4096,2048] = A * W,  B pre-transposed (Wt[n][k]).
// TERMS=3: C = AhBh + AhBl + AlBh   (score path)
// TERMS=2: C = AhBh + AlBh          (A split, B single)
// TERMS=1: C = AhBh                 (both single)
// MODE: 0 fp32 row-major; 1 fp32 scatter (b,h,s,d); 2 fp16 scatter.
#define GBK 32
#define ROWB 80
#define T_A  (128 * ROWB)
#define NCH (HIDDEN / GBK)
#define GEMM_SMEM3 (2 * 4 * T_A)   // 81920
#define GEMM_SMEM1 (2 * 2 * T_A)   // 40960

template<int MODE, int TERMS>
__global__ __launch_bounds__(256) void gemm_hmma(
    const __half* __restrict__ Ahp, const __half* __restrict__ Alp,
    const __half* __restrict__ Bhp, const __half* __restrict__ Blp,
    void* __restrict__ outv)
{
    constexpr int NTILES = (TERMS == 3) ? 4 : (TERMS == 2 ? 3 : 2);
    constexpr int SSTR   = NTILES * T_A;
    constexpr int OFF_AH = 0;
    constexpr int OFF_AL = T_A;                               // valid if TERMS>=2
    constexpr int OFF_BH = (TERMS >= 2 ? 2 : 1) * T_A;
    constexpr int OFF_BL = 3 * T_A;                           // valid if TERMS==3

    extern __shared__ char smem[];
    const uint32_t sb = smem_u32(smem);
    const int tid = threadIdx.x;
    const int lane = tid & 31;
    const int warpId = tid >> 5;
    const int warpM = warpId >> 2;
    const int warpN = warpId & 3;
    const int rowBase = blockIdx.y * 128;
    const int colBase = blockIdx.x * 128;

    const int lr = lane & 15;
    const int lc = lane >> 4;

    float acc[4][4][4];
#pragma unroll
    for (int mt = 0; mt < 4; mt++)
#pragma unroll
        for (int nn = 0; nn < 4; nn++)
#pragma unroll
            for (int e = 0; e < 4; e++) acc[mt][nn][e] = 0.f;

    auto load_stage = [&](int buf, int chunk) {
        uint32_t base = sb + buf * SSTR;
        int kb = chunk * GBK;
#pragma unroll
        for (int i = 0; i < 2; i++) {
            int c4 = tid + 256 * i;
            int r = c4 >> 2, o = c4 & 3;
            uint32_t d = r * ROWB + o * 16;
            size_t sA = (size_t)(rowBase + r) * HIDDEN + kb + o * 8;
            size_t sB = (size_t)(colBase + r) * HIDDEN + kb + o * 8;
            cp16(base + OFF_AH + d, Ahp + sA);
            if (TERMS >= 2) cp16(base + OFF_AL + d, Alp + sA);
            cp16(base + OFF_BH + d, Bhp + sB);
            if (TERMS == 3) cp16(base + OFF_BL + d, Blp + sB);
        }
        cp_commit();
    };

    load_stage(0, 0);
    load_stage(1, 1);

    for (int c = 0; c < NCH; c++) {
        if (c < NCH - 2) asm volatile("cp.async.wait_group 1;" ::: "memory");
        else             asm volatile("cp.async.wait_group 0;" ::: "memory");
        __syncthreads();

        uint32_t st = sb + (c & 1) * SSTR;
#pragma unroll
        for (int k16 = 0; k16 < 2; k16++) {
            const uint32_t kbyte = (k16 * 16 + lc * 8) * 2;
            uint32_t ah[4][4], al[4][4], bh[2][4], bl[2][4];
#pragma unroll
            for (int mt = 0; mt < 4; mt++) {
                uint32_t ro = (warpM * 64 + mt * 16 + lr) * ROWB + kbyte;
                ldsm4(ah[mt], st + OFF_AH + ro);
                if (TERMS >= 2) ldsm4(al[mt], st + OFF_AL + ro);
            }
#pragma unroll
            for (int nt = 0; nt < 2; nt++) {
                uint32_t ro = (warpN * 32 + nt * 16 + lr) * ROWB + kbyte;
                ldsm4(bh[nt], st + OFF_BH + ro);
                if (TERMS == 3) ldsm4(bl[nt], st + OFF_BL + ro);
            }
#pragma unroll
            for (int mt = 0; mt < 4; mt++)
#pragma unroll
                for (int nn = 0; nn < 4; nn++) {
                    int nt = nn >> 1, hf = nn & 1;
                    mma_f16(acc[mt][nn], ah[mt], bh[nt][hf], bh[nt][hf + 2]);
                    if (TERMS == 3)
                        mma_f16(acc[mt][nn], ah[mt], bl[nt][hf], bl[nt][hf + 2]);
                    if (TERMS >= 2)
                        mma_f16(acc[mt][nn], al[mt], bh[nt][hf], bh[nt][hf + 2]);
                }
        }
        __syncthreads();
        if (c + 2 < NCH) load_stage(c & 1, c + 2);
    }

    const int er = lane >> 2, ec = (lane & 3) * 2;
#pragma unroll
    for (int mt = 0; mt < 4; mt++) {
#pragma unroll
        for (int nn = 0; nn < 4; nn++) {
            int col = colBase + warpN * 32 + nn * 8 + ec;
#pragma unroll
            for (int hf = 0; hf < 2; hf++) {
                int row = rowBase + warpM * 64 + mt * 16 + er + hf * 8;
                float v0 = acc[mt][nn][2 * hf];
                float v1 = acc[mt][nn][2 * hf + 1];
                if (MODE == 0) {
                    *(float2*)((float*)outv + (size_t)row * HIDDEN + col) = make_float2(v0, v1);
                } else if (MODE == 1) {
                    int b = row >> 11, s = row & (SEQ - 1);
                    int h = col >> 7, d = col & (HD - 1);
                    *(float2*)((float*)outv + (((size_t)b * NH + h) * SEQ + s) * HD + d) =
                        make_float2(v0, v1);
                } else {
                    int b = row >> 11, s = row & (SEQ - 1);
                    int h = col >> 7, d = col & (HD - 1);
                    *(uint32_t*)((__half*)outv + (((size_t)b * NH + h) * SEQ + s) * HD + d) =
                        packh2(v0, v1);
                }
            }
        }
    }
}

// ---------------- fp16 HMMA flash attention ----------------------------------
// QK^T: 3 products (QhKh + QhKl + QlKh); PV: 1 product (P single, V single).
#define ROWP 272
#define KTILE (64 * ROWP)
#define QBYTES (128 * ROWP)
#define STG (3 * KTILE)                      // Kh, Kl, V
#define ATTN_SMEM (2 * QBYTES + 2 * STG)     // 174080

__global__ __launch_bounds__(256, 1) void attn_tc(
    const __half* __restrict__ qh, const __half* __restrict__ ql,
    const __half* __restrict__ kh, const __half* __restrict__ kl,
    const __half* __restrict__ vh,
    __half* __restrict__ outh)
{
    extern __shared__ char sm[];
    const uint32_t sb = smem_u32(sm);
    const int tid = threadIdx.x;
    const int lane = tid & 31;
    const int w = tid >> 5;
    const int qt = blockIdx.x;
    const int bh = blockIdx.y;
    const size_t headOff = (size_t)bh * SEQ * HD;

    const uint32_t qsh = sb, qsl = sb + QBYTES;
    const uint32_t kvb0 = sb + 2 * QBYTES;

    {
        const __half* qhp = qh + headOff + (size_t)qt * 128 * HD;
        const __half* qlp = ql + headOff + (size_t)qt * 128 * HD;
#pragma unroll
        for (int i = 0; i < 8; i++) {
            int idx = tid + 256 * i;
            int r = idx >> 4, o = idx & 15;
            uint32_t d = r * ROWP + o * 16;
            size_t s = (size_t)r * HD + o * 8;
            cp16(qsh + d, qhp + s);
            cp16(qsl + d, qlp + s);
        }
        cp_commit();
    }

#define LOAD_KV(buf, t) do {                                                   \
        uint32_t base = kvb0 + (buf) * STG;                                    \
        size_t rb = headOff + (size_t)(t) * 64 * HD;                           \
        _Pragma("unroll")                                                      \
        for (int i = 0; i < 4; i++) {                                          \
            int idx = tid + 256 * i;                                           \
            int r = idx >> 4, o = idx & 15;                                    \
            uint32_t d = r * ROWP + o * 16;                                    \
            size_t s = rb + (size_t)r * HD + o * 8;                            \
            cp16(base + d,             kh + s);                                \
            cp16(base + KTILE + d,     kl + s);                                \
            cp16(base + 2 * KTILE + d, vh + s);                                \
        }                                                                      \
        cp_commit();                                                           \
    } while (0)

    LOAD_KV(0, 0);
    LOAD_KV(1, 1);

    const int wq0 = w * 16;
    const uint32_t qoff = (uint32_t)(wq0 + (lane & 15)) * ROWP + ((lane >> 4) << 4);
    const uint32_t krow = (lane & 7) + ((lane >> 4) << 3);
    const uint32_t kcb  = ((lane >> 3) & 1) << 4;
    const uint32_t vrow = (lane & 7) + (((lane >> 3) & 1) << 3);
    const uint32_t vcb  = (lane >> 4) << 4;

    float m0 = -1e30f, m1 = -1e30f, l0 = 0.f, l1 = 0.f;
    float o[16][4];
#pragma unroll
    for (int t = 0; t < 16; t++)
#pragma unroll
        for (int e = 0; e < 4; e++) o[t][e] = 0.f;

    const int NT = SEQ / 64;
    for (int t = 0; t < NT; t++) {
        if (t < NT - 2) asm volatile("cp.async.wait_group 1;" ::: "memory");
        else            asm volatile("cp.async.wait_group 0;" ::: "memory");
        __syncthreads();

        const uint32_t kb = kvb0 + (t & 1) * STG;

        float sc[8][4];
#pragma unroll
        for (int tt = 0; tt < 8; tt++)
#pragma unroll
            for (int e = 0; e < 4; e++) sc[tt][e] = 0.f;

#pragma unroll
        for (int kg = 0; kg < 8; kg++) {
            uint32_t aqh[4], aql4[4];
            ldsm4(aqh,  qsh + qoff + kg * 32);
            ldsm4(aql4, qsl + qoff + kg * 32);
#pragma unroll
            for (int ng = 0; ng < 4; ng++) {
                uint32_t kh4[4], kl4[4];
                uint32_t ka = kb + (ng * 16 + krow) * ROWP + kcb + kg * 32;
                ldsm4(kh4, ka);
                ldsm4(kl4, ka + KTILE);
                mma_f16(sc[2 * ng],     aqh,  kh4[0], kh4[1]);
                mma_f16(sc[2 * ng + 1], aqh,  kh4[2], kh4[3]);
                mma_f16(sc[2 * ng],     aqh,  kl4[0], kl4[1]);
                mma_f16(sc[2 * ng + 1], aqh,  kl4[2], kl4[3]);
                mma_f16(sc[2 * ng],     aql4, kh4[0], kh4[1]);
                mma_f16(sc[2 * ng + 1], aql4, kh4[2], kh4[3]);
            }
        }

        float mx0 = -1e30f, mx1 = -1e30f;
#pragma unroll
        for (int tt = 0; tt < 8; tt++) {
            mx0 = fmaxf(mx0, fmaxf(sc[tt][0], sc[tt][1]));
            mx1 = fmaxf(mx1, fmaxf(sc[tt][2], sc[tt][3]));
        }
        mx0 = fmaxf(mx0, __shfl_xor_sync(0xffffffffu, mx0, 1));
        mx0 = fmaxf(mx0, __shfl_xor_sync(0xffffffffu, mx0, 2));
        mx1 = fmaxf(mx1, __shfl_xor_sync(0xffffffffu, mx1, 1));
        mx1 = fmaxf(mx1, __shfl_xor_sync(0xffffffffu, mx1, 2));

        float nm0 = fmaxf(m0, mx0), nm1 = fmaxf(m1, mx1);
        float c0 = exp2p(m0 - nm0), c1 = exp2p(m1 - nm1);
        m0 = nm0; m1 = nm1;

        uint32_t pah[4][4];
        float rs0 = 0.f, rs1 = 0.f;
#pragma unroll
        for (int tt = 0; tt < 8; tt++) {
            float p0 = exp2p(sc[tt][0] - m0);
            float p1 = exp2p(sc[tt][1] - m0);
            float p2 = exp2p(sc[tt][2] - m1);
            float p3 = exp2p(sc[tt][3] - m1);
            rs0 += p0 + p1;
            rs1 += p2 + p3;
            int g = tt >> 1, ri = (tt & 1) * 2;
            pah[g][ri]     = packh2(p0, p1);
            pah[g][ri + 1] = packh2(p2, p3);
        }
        rs0 += __shfl_xor_sync(0xffffffffu, rs0, 1);
        rs0 += __shfl_xor_sync(0xffffffffu, rs0, 2);
        rs1 += __shfl_xor_sync(0xffffffffu, rs1, 1);
        rs1 += __shfl_xor_sync(0xffffffffu, rs1, 2);
        l0 = l0 * c0 + rs0;
        l1 = l1 * c1 + rs1;

#pragma unroll
        for (int tt = 0; tt < 16; tt++) {
            o[tt][0] *= c0; o[tt][1] *= c0;
            o[tt][2] *= c1; o[tt][3] *= c1;
        }

#pragma unroll
        for (int g = 0; g < 4; g++) {
#pragma unroll
            for (int dg = 0; dg < 8; dg++) {
                uint32_t v4[4];
                uint32_t va = kb + 2 * KTILE + (g * 16 + vrow) * ROWP + vcb + dg * 32;
                ldsm4t(v4, va);
                mma_f16(o[2 * dg],     pah[g], v4[0], v4[1]);
                mma_f16(o[2 * dg + 1], pah[g], v4[2], v4[3]);
            }
        }
        __syncthreads();
        if (t + 2 < NT) LOAD_KV(t & 1, t + 2);
    }
#undef LOAD_KV

    float il0 = 1.0f / l0, il1 = 1.0f / l1;
    int b = bh >> 4, h = bh & 15;
    int s0 = qt * 128 + wq0 + (lane >> 2);
    int s1 = s0 + 8;
    size_t row0 = ((size_t)b * SEQ + s0) * HIDDEN + h * HD;
    size_t row1 = ((size_t)b * SEQ + s1) * HIDDEN + h * HD;
    int dc = (lane & 3) * 2;
#pragma unroll
    for (int tt = 0; tt < 16; tt++) {
        int d = tt * 8 + dc;
        *(uint32_t*)(outh + row0 + d) = packh2(o[tt][0] * il0, o[tt][1] * il0);
        *(uint32_t*)(outh + row1 + d) = packh2(o[tt][2] * il1, o[tt][3] * il1);
    }
}

// ---------------------------------------------------------------------------
extern "C" void kernel_launch(void* const* d_in, const int* in_sizes, int n_in,
                              void* d_out, int out_size)
{
    const float* hidden = (const float*)d_in[0];
    const int*   posids = (const int*)d_in[1];
    const float* wq = (const float*)d_in[2];
    const float* wk = (const float*)d_in[3];
    const float* wv = (const float*)d_in[4];
    const float* wo = (const float*)d_in[5];
    float* out = (float*)d_out;

    float *q, *k;
    __half *ah, *al, *whi, *wlo, *qhp, *qlp, *khp, *klp, *vhp;
    cudaGetSymbolAddress((void**)&q, g_q);
    cudaGetSymbolAddress((void**)&k, g_k);
    cudaGetSymbolAddress((void**)&ah, g_ah);
    cudaGetSymbolAddress((void**)&al, g_al);
    cudaGetSymbolAddress((void**)&whi, g_whi);
    cudaGetSymbolAddress((void**)&wlo, g_wlo);
    cudaGetSymbolAddress((void**)&qhp, g_qh);
    cudaGetSymbolAddress((void**)&qlp, g_ql);
    cudaGetSymbolAddress((void**)&khp, g_kh);
    cudaGetSymbolAddress((void**)&klp, g_kl);
    cudaGetSymbolAddress((void**)&vhp, g_vh);
    const size_t wstep = (size_t)HIDDEN * HIDDEN;

    cudaFuncSetAttribute(gemm_hmma<1,3>, cudaFuncAttributeMaxDynamicSharedMemorySize, GEMM_SMEM3);
    cudaFuncSetAttribute(gemm_hmma<2,1>, cudaFuncAttributeMaxDynamicSharedMemorySize, GEMM_SMEM1);
    cudaFuncSetAttribute(gemm_hmma<0,1>, cudaFuncAttributeMaxDynamicSharedMemorySize, GEMM_SMEM1);
    cudaFuncSetAttribute(attn_tc, cudaFuncAttributeMaxDynamicSharedMemorySize, ATTN_SMEM);

    // packs
    pack_hl<<<(MROWS * HIDDEN) / 1024, 256>>>(hidden, ah, al);
    dim3 wg(HIDDEN / 32, HIDDEN / 32);
    pack_wT<1><<<wg, dim3(32, 8)>>>(wq, whi + 0 * wstep, wlo + 0 * wstep);
    pack_wT<1><<<wg, dim3(32, 8)>>>(wk, whi + 1 * wstep, wlo + 1 * wstep);
    pack_wT<0><<<wg, dim3(32, 8)>>>(wv, whi + 2 * wstep, nullptr);
    pack_wT<0><<<wg, dim3(32, 8)>>>(wo, whi + 3 * wstep, nullptr);

    dim3 gg(HIDDEN / 128, MROWS / 128);

    // projections: Q,K 3-term fp32 scatter; V 1-term fp16 scatter
    gemm_hmma<1,3><<<gg, 256, GEMM_SMEM3>>>(ah, al, whi + 0 * wstep, wlo + 0 * wstep, q);
    gemm_hmma<1,3><<<gg, 256, GEMM_SMEM3>>>(ah, al, whi + 1 * wstep, wlo + 1 * wstep, k);
    gemm_hmma<2,1><<<gg, 256, GEMM_SMEM1>>>(ah, nullptr, whi + 2 * wstep, nullptr, vhp);

    // RoPE + fp16 hi/lo pack
    dim3 rg(SEQ / 4, BATCH * NH);
    rope_pack<<<rg, 256>>>(q, posids, qhp, qlp, QSC);
    rope_pack<<<rg, 256>>>(k, posids, khp, klp, 1.0f);

    // attention -> writes single fp16 into O-proj A buffer
    dim3 ag(SEQ / 128, BATCH * NH);
    attn_tc<<<ag, 256, ATTN_SMEM>>>(qhp, qlp, khp, klp, vhp, ah);

    // O projection (1-term, fp32 row-major out)
    gemm_hmma<0,1><<<gg, 256, GEMM_SMEM1>>>(ah, nullptr, whi + 3 * wstep, nullptr, out);
}

// round 8
// speedup vs baseline: 4.2909x; 1.0628x over previous
#include <cuda_runtime.h>
#include <cuda_fp16.h>
#include <math.h>
#include <stdint.h>

#define HIDDEN 2048
#define NH 16
#define HD 128
#define BATCH 2
#define SEQ 2048
#define MROWS (BATCH*SEQ)   // 4096

// 1/sqrt(128) * log2(e)
#define QSC 0.1275174277f

// ---------------- scratch (device globals) ----------------------------------
__device__ __half g_ah[(size_t)MROWS*HIDDEN];      // A hi (hidden / attn out)
__device__ __half g_al[(size_t)MROWS*HIDDEN];      // A lo (hidden only)
__device__ __half g_whi[4][(size_t)HIDDEN*HIDDEN]; // W^T hi (q,k,v,o)
__device__ __half g_wlo[2][(size_t)HIDDEN*HIDDEN]; // W^T lo (q,k only)

__device__ __half g_qh[(size_t)BATCH*NH*SEQ*HD];   // roped+scaled Q hi/lo
__device__ __half g_ql[(size_t)BATCH*NH*SEQ*HD];
__device__ __half g_kh[(size_t)BATCH*NH*SEQ*HD];   // roped K hi/lo
__device__ __half g_kl[(size_t)BATCH*NH*SEQ*HD];
__device__ __half g_vh[(size_t)BATCH*NH*SEQ*HD];   // V single fp16

__device__ float g_cs[(size_t)SEQ*64];             // RoPE cos table
__device__ float g_sn[(size_t)SEQ*64];             // RoPE sin table

// ---------------- PTX helpers ------------------------------------------------
__device__ __forceinline__ uint32_t smem_u32(const void* p) {
    uint32_t a;
    asm("{ .reg .u64 t; cvta.to.shared.u64 t, %1; cvt.u32.u64 %0, t; }" : "=r"(a) : "l"(p));
    return a;
}
__device__ __forceinline__ void cp16(uint32_t dst, const void* src) {
    asm volatile("cp.async.cg.shared.global [%0], [%1], 16;" :: "r"(dst), "l"(src));
}
__device__ __forceinline__ void cp_commit() { asm volatile("cp.async.commit_group;"); }

__device__ __forceinline__ void ldsm4(uint32_t* r, uint32_t addr) {
    asm volatile("ldmatrix.sync.aligned.m8n8.x4.shared.b16 {%0,%1,%2,%3}, [%4];"
                 : "=r"(r[0]), "=r"(r[1]), "=r"(r[2]), "=r"(r[3]) : "r"(addr));
}
__device__ __forceinline__ void ldsm4t(uint32_t* r, uint32_t addr) {
    asm volatile("ldmatrix.sync.aligned.m8n8.x4.trans.shared.b16 {%0,%1,%2,%3}, [%4];"
                 : "=r"(r[0]), "=r"(r[1]), "=r"(r[2]), "=r"(r[3]) : "r"(addr));
}
__device__ __forceinline__ void mma_f16(float* c, const uint32_t* a, uint32_t b0, uint32_t b1) {
    asm volatile(
        "mma.sync.aligned.m16n8k16.row.col.f32.f16.f16.f32 "
        "{%0,%1,%2,%3}, {%4,%5,%6,%7}, {%8,%9}, {%0,%1,%2,%3};"
        : "+f"(c[0]), "+f"(c[1]), "+f"(c[2]), "+f"(c[3])
        : "r"(a[0]), "r"(a[1]), "r"(a[2]), "r"(a[3]), "r"(b0), "r"(b1));
}
__device__ __forceinline__ uint32_t packh2(float lo, float hi) {
    uint32_t r;
    asm("cvt.rn.f16x2.f32 %0, %1, %2;" : "=r"(r) : "f"(hi), "f"(lo));
    return r;
}
// fast 2^x on FMA pipe, x <= 0
__device__ __forceinline__ float exp2p(float x) {
    x = fmaxf(x, -120.0f);
    float n = rintf(x);
    float f = x - n;
    float p = fmaf(f, 0.0013333558f, 0.0096181291f);
    p = fmaf(f, p, 0.0555041087f);
    p = fmaf(f, p, 0.2402265070f);
    p = fmaf(f, p, 0.6931471806f);
    p = fmaf(f, p, 1.0f);
    return __int_as_float(__float_as_int(p) + ((int)n << 23));
}

// ---------------- small kernels ----------------------------------------------
__global__ __launch_bounds__(256) void pack_hl(const float* __restrict__ src,
                                               __half* __restrict__ hi,
                                               __half* __restrict__ lo)
{
    size_t i = ((size_t)blockIdx.x * 256 + threadIdx.x) * 4;
    float4 v = *(const float4*)(src + i);
    __half h[4], l[4];
    const float* f = (const float*)&v;
#pragma unroll
    for (int e = 0; e < 4; e++) {
        h[e] = __float2half_rn(f[e]);
        l[e] = __float2half_rn(f[e] - __half2float(h[e]));
    }
    *(uint2*)(hi + i) = *(uint2*)h;
    *(uint2*)(lo + i) = *(uint2*)l;
}

template<int SPLIT>
__global__ __launch_bounds__(256) void pack_wT(const float* __restrict__ W,
                                               __half* __restrict__ th,
                                               __half* __restrict__ tl)
{
    __shared__ float t[32][33];
    int n0 = blockIdx.x * 32, k0 = blockIdx.y * 32;
    int tx = threadIdx.x, ty = threadIdx.y;   // (32, 8)
#pragma unroll
    for (int j = 0; j < 4; j++)
        t[ty + 8 * j][tx] = W[(size_t)(k0 + ty + 8 * j) * HIDDEN + n0 + tx];
    __syncthreads();
#pragma unroll
    for (int j = 0; j < 4; j++) {
        float x = t[tx][ty + 8 * j];
        __half h = __float2half_rn(x);
        size_t o = (size_t)(n0 + ty + 8 * j) * HIDDEN + k0 + tx;
        th[o] = h;
        if (SPLIT) tl[o] = __float2half_rn(x - __half2float(h));
    }
}

// cos/sin table, bit-identical formulas to the previous rope kernel
__global__ __launch_bounds__(256) void rope_tab(const int* __restrict__ pos_ids,
                                                float* __restrict__ cs,
                                                float* __restrict__ sn)
{
    int i = blockIdx.x * 256 + threadIdx.x;   // < SEQ*64
    int s = i >> 6, j = i & 63;
    int pos = pos_ids[s];
    float t = powf(10000.0f, (float)(2 * j) * (1.0f / 128.0f));
    float ang = (float)pos * (1.0f / t);
    float sv, cv;
    sincosf(ang, &sv, &cv);
    cs[i] = cv;
    sn[i] = sv;
}

// ---------------- GEMM common tile constants --------------------------------
#define GBK 32
#define ROWB 80
#define T_A  (128 * ROWB)          // 10240 B per operand tile
#define NCH (HIDDEN / GBK)         // 64
#define GEMM_QK_SMEM (3 * 4 * T_A) // 122880 (3 stages x {Ah,Al,Bh,Bl})
#define GEMM1_SMEM   (3 * 2 * T_A) // 61440  (3 stages x {Ah,Bh})

#define WAIT_3STAGE(c)                                                \
    do {                                                              \
        if ((c) + 3 <= NCH)      asm volatile("cp.async.wait_group 2;" ::: "memory"); \
        else if ((c) + 2 == NCH) asm volatile("cp.async.wait_group 1;" ::: "memory"); \
        else                     asm volatile("cp.async.wait_group 0;" ::: "memory"); \
    } while (0)

// ---------------- fused Q+K projection (3-term) + RoPE epilogue --------------
// grid (16, 32, 2): x=head(col tile), y=row tile, z: 0=Q (scale=QSC), 1=K.
__global__ __launch_bounds__(256, 1) void gemm_qk3(
    const __half* __restrict__ Ahp, const __half* __restrict__ Alp,
    const __half* __restrict__ Whi, const __half* __restrict__ Wlo,
    const float* __restrict__ cs, const float* __restrict__ sn,
    __half* __restrict__ qh, __half* __restrict__ ql,
    __half* __restrict__ kh, __half* __restrict__ kl)
{
    constexpr int SSTR = 4 * T_A;
    constexpr int OFF_AH = 0, OFF_AL = T_A, OFF_BH = 2 * T_A, OFF_BL = 3 * T_A;

    extern __shared__ char smem[];
    const uint32_t sb = smem_u32(smem);
    const int tid = threadIdx.x;
    const int lane = tid & 31;
    const int warpId = tid >> 5;
    const int warpM = warpId >> 2;
    const int warpN = warpId & 3;
    const int head = blockIdx.x;
    const int rowBase = blockIdx.y * 128;
    const int colBase = head * 128;
    const int z = blockIdx.z;

    const __half* Bhp = Whi + (size_t)z * HIDDEN * HIDDEN;
    const __half* Blp = Wlo + (size_t)z * HIDDEN * HIDDEN;
    __half* oh = z ? kh : qh;
    __half* ol = z ? kl : ql;
    const float scale = z ? 1.0f : QSC;

    const int lr = lane & 15;
    const int lc = lane >> 4;

    float acc[4][4][4];
#pragma unroll
    for (int mt = 0; mt < 4; mt++)
#pragma unroll
        for (int nn = 0; nn < 4; nn++)
#pragma unroll
            for (int e = 0; e < 4; e++) acc[mt][nn][e] = 0.f;

    auto load_stage = [&](int buf, int chunk) {
        uint32_t base = sb + buf * SSTR;
        int kb = chunk * GBK;
#pragma unroll
        for (int i = 0; i < 2; i++) {
            int c4 = tid + 256 * i;
            int r = c4 >> 2, o = c4 & 3;
            uint32_t d = r * ROWB + o * 16;
            size_t sA = (size_t)(rowBase + r) * HIDDEN + kb + o * 8;
            size_t sB = (size_t)(colBase + r) * HIDDEN + kb + o * 8;
            cp16(base + OFF_AH + d, Ahp + sA);
            cp16(base + OFF_AL + d, Alp + sA);
            cp16(base + OFF_BH + d, Bhp + sB);
            cp16(base + OFF_BL + d, Blp + sB);
        }
        cp_commit();
    };

    load_stage(0, 0);
    load_stage(1, 1);
    load_stage(2, 2);

    for (int c = 0; c < NCH; c++) {
        WAIT_3STAGE(c);
        __syncthreads();

        uint32_t st = sb + (c % 3) * SSTR;
#pragma unroll
        for (int k16 = 0; k16 < 2; k16++) {
            const uint32_t kbyte = (k16 * 16 + lc * 8) * 2;
            uint32_t ah[4][4], al[4][4], bh[2][4], bl[2][4];
#pragma unroll
            for (int mt = 0; mt < 4; mt++) {
                uint32_t ro = (warpM * 64 + mt * 16 + lr) * ROWB + kbyte;
                ldsm4(ah[mt], st + OFF_AH + ro);
                ldsm4(al[mt], st + OFF_AL + ro);
            }
#pragma unroll
            for (int nt = 0; nt < 2; nt++) {
                uint32_t ro = (warpN * 32 + nt * 16 + lr) * ROWB + kbyte;
                ldsm4(bh[nt], st + OFF_BH + ro);
                ldsm4(bl[nt], st + OFF_BL + ro);
            }
#pragma unroll
            for (int mt = 0; mt < 4; mt++)
#pragma unroll
                for (int nn = 0; nn < 4; nn++) {
                    int nt = nn >> 1, hf = nn & 1;
                    mma_f16(acc[mt][nn], ah[mt], bh[nt][hf], bh[nt][hf + 2]);
                    mma_f16(acc[mt][nn], ah[mt], bl[nt][hf], bl[nt][hf + 2]);
                    mma_f16(acc[mt][nn], al[mt], bh[nt][hf], bh[nt][hf + 2]);
                }
        }
        __syncthreads();
        if (c + 3 < NCH) load_stage(c % 3, c + 3);
    }

    // ---- stage acc (fp32) through smem, then RoPE + hi/lo split + store ----
    float* fs = (float*)smem;                 // [128][132]
    const int er = lane >> 2, ec = (lane & 3) * 2;
#pragma unroll
    for (int mt = 0; mt < 4; mt++)
#pragma unroll
        for (int nn = 0; nn < 4; nn++) {
            int col = warpN * 32 + nn * 8 + ec;
#pragma unroll
            for (int hf = 0; hf < 2; hf++) {
                int r = warpM * 64 + mt * 16 + er + hf * 8;
                fs[r * 132 + col]     = acc[mt][nn][2 * hf];
                fs[r * 132 + col + 1] = acc[mt][nn][2 * hf + 1];
            }
        }
    __syncthreads();

    const int tc = tid & 15, tr = tid >> 4;
    const int d0 = tc * 4;                    // pair-dim 0..60
#pragma unroll
    for (int rr = 0; rr < 8; rr++) {
        int r = tr * 8 + rr;
        int grow = rowBase + r;
        int b = grow >> 11, s = grow & (SEQ - 1);
        float4 y1 = *(float4*)&fs[r * 132 + d0];
        float4 y2 = *(float4*)&fs[r * 132 + d0 + 64];
        float4 c4 = *(const float4*)&cs[(size_t)s * 64 + d0];
        float4 s4 = *(const float4*)&sn[(size_t)s * 64 + d0];

        float o1[4], o2[4];
        o1[0] = (y1.x * c4.x - y2.x * s4.x) * scale;
        o1[1] = (y1.y * c4.y - y2.y * s4.y) * scale;
        o1[2] = (y1.z * c4.z - y2.z * s4.z) * scale;
        o1[3] = (y1.w * c4.w - y2.w * s4.w) * scale;
        o2[0] = (y2.x * c4.x + y1.x * s4.x) * scale;
        o2[1] = (y2.y * c4.y + y1.y * s4.y) * scale;
        o2[2] = (y2.z * c4.z + y1.z * s4.z) * scale;
        o2[3] = (y2.w * c4.w + y1.w * s4.w) * scale;

        size_t base = (((size_t)b * NH + head) * SEQ + s) * HD + d0;
        uint32_t h1a = packh2(o1[0], o1[1]), h1b = packh2(o1[2], o1[3]);
        uint32_t h2a = packh2(o2[0], o2[1]), h2b = packh2(o2[2], o2[3]);
        *(uint2*)(oh + base)      = make_uint2(h1a, h1b);
        *(uint2*)(oh + base + 64) = make_uint2(h2a, h2b);

        __half2 v1a = *(__half2*)&h1a, v1b = *(__half2*)&h1b;
        __half2 v2a = *(__half2*)&h2a, v2b = *(__half2*)&h2b;
        uint32_t l1a = packh2(o1[0] - __low2float(v1a), o1[1] - __high2float(v1a));
        uint32_t l1b = packh2(o1[2] - __low2float(v1b), o1[3] - __high2float(v1b));
        uint32_t l2a = packh2(o2[0] - __low2float(v2a), o2[1] - __high2float(v2a));
        uint32_t l2b = packh2(o2[2] - __low2float(v2b), o2[3] - __high2float(v2b));
        *(uint2*)(ol + base)      = make_uint2(l1a, l1b);
        *(uint2*)(ol + base + 64) = make_uint2(l2a, l2b);
    }
}

// ---------------- 1-term fp16 GEMM (V-proj, O-proj) --------------------------
// MODE: 0 fp32 row-major; 2 fp16 scatter (b,h,s,d).
template<int MODE>
__global__ __launch_bounds__(256, 2) void gemm_hmma1(
    const __half* __restrict__ Ahp, const __half* __restrict__ Bhp,
    void* __restrict__ outv)
{
    constexpr int SSTR = 2 * T_A;
    constexpr int OFF_AH = 0, OFF_BH = T_A;

    extern __shared__ char smem[];
    const uint32_t sb = smem_u32(smem);
    const int tid = threadIdx.x;
    const int lane = tid & 31;
    const int warpId = tid >> 5;
    const int warpM = warpId >> 2;
    const int warpN = warpId & 3;
    const int rowBase = blockIdx.y * 128;
    const int colBase = blockIdx.x * 128;

    const int lr = lane & 15;
    const int lc = lane >> 4;

    float acc[4][4][4];
#pragma unroll
    for (int mt = 0; mt < 4; mt++)
#pragma unroll
        for (int nn = 0; nn < 4; nn++)
#pragma unroll
            for (int e = 0; e < 4; e++) acc[mt][nn][e] = 0.f;

    auto load_stage = [&](int buf, int chunk) {
        uint32_t base = sb + buf * SSTR;
        int kb = chunk * GBK;
#pragma unroll
        for (int i = 0; i < 2; i++) {
            int c4 = tid + 256 * i;
            int r = c4 >> 2, o = c4 & 3;
            uint32_t d = r * ROWB + o * 16;
            cp16(base + OFF_AH + d, Ahp + (size_t)(rowBase + r) * HIDDEN + kb + o * 8);
            cp16(base + OFF_BH + d, Bhp + (size_t)(colBase + r) * HIDDEN + kb + o * 8);
        }
        cp_commit();
    };

    load_stage(0, 0);
    load_stage(1, 1);
    load_stage(2, 2);

    for (int c = 0; c < NCH; c++) {
        WAIT_3STAGE(c);
        __syncthreads();

        uint32_t st = sb + (c % 3) * SSTR;
#pragma unroll
        for (int k16 = 0; k16 < 2; k16++) {
            const uint32_t kbyte = (k16 * 16 + lc * 8) * 2;
            uint32_t ah[4][4], bh[2][4];
#pragma unroll
            for (int mt = 0; mt < 4; mt++)
                ldsm4(ah[mt], st + OFF_AH + (warpM * 64 + mt * 16 + lr) * ROWB + kbyte);
#pragma unroll
            for (int nt = 0; nt < 2; nt++)
                ldsm4(bh[nt], st + OFF_BH + (warpN * 32 + nt * 16 + lr) * ROWB + kbyte);
#pragma unroll
            for (int mt = 0; mt < 4; mt++)
#pragma unroll
                for (int nn = 0; nn < 4; nn++) {
                    int nt = nn >> 1, hf = nn & 1;
                    mma_f16(acc[mt][nn], ah[mt], bh[nt][hf], bh[nt][hf + 2]);
                }
        }
        __syncthreads();
        if (c + 3 < NCH) load_stage(c % 3, c + 3);
    }

    const int er = lane >> 2, ec = (lane & 3) * 2;
#pragma unroll
    for (int mt = 0; mt < 4; mt++) {
#pragma unroll
        for (int nn = 0; nn < 4; nn++) {
            int col = colBase + warpN * 32 + nn * 8 + ec;
#pragma unroll
            for (int hf = 0; hf < 2; hf++) {
                int row = rowBase + warpM * 64 + mt * 16 + er + hf * 8;
                float v0 = acc[mt][nn][2 * hf];
                float v1 = acc[mt][nn][2 * hf + 1];
                if (MODE == 0) {
                    *(float2*)((float*)outv + (size_t)row * HIDDEN + col) = make_float2(v0, v1);
                } else {
                    int b = row >> 11, s = row & (SEQ - 1);
                    int h = col >> 7, d = col & (HD - 1);
                    *(uint32_t*)((__half*)outv + (((size_t)b * NH + h) * SEQ + s) * HD + d) =
                        packh2(v0, v1);
                }
            }
        }
    }
}

// ---------------- fp16 HMMA flash attention (validated R7) -------------------
#define ROWP 272
#define KTILE (64 * ROWP)
#define QBYTES (128 * ROWP)
#define STG (3 * KTILE)                      // Kh, Kl, V
#define ATTN_SMEM (2 * QBYTES + 2 * STG)     // 174080

__global__ __launch_bounds__(256, 1) void attn_tc(
    const __half* __restrict__ qh, const __half* __restrict__ ql,
    const __half* __restrict__ kh, const __half* __restrict__ kl,
    const __half* __restrict__ vh,
    __half* __restrict__ outh)
{
    extern __shared__ char sm[];
    const uint32_t sb = smem_u32(sm);
    const int tid = threadIdx.x;
    const int lane = tid & 31;
    const int w = tid >> 5;
    const int qt = blockIdx.x;
    const int bh = blockIdx.y;
    const size_t headOff = (size_t)bh * SEQ * HD;

    const uint32_t qsh = sb, qsl = sb + QBYTES;
    const uint32_t kvb0 = sb + 2 * QBYTES;

    {
        const __half* qhp = qh + headOff + (size_t)qt * 128 * HD;
        const __half* qlp = ql + headOff + (size_t)qt * 128 * HD;
#pragma unroll
        for (int i = 0; i < 8; i++) {
            int idx = tid + 256 * i;
            int r = idx >> 4, o = idx & 15;
            uint32_t d = r * ROWP + o * 16;
            size_t s = (size_t)r * HD + o * 8;
            cp16(qsh + d, qhp + s);
            cp16(qsl + d, qlp + s);
        }
        cp_commit();
    }

#define LOAD_KV(buf, t) do {                                                   \
        uint32_t base = kvb0 + (buf) * STG;                                    \
        size_t rb = headOff + (size_t)(t) * 64 * HD;                           \
        _Pragma("unroll")                                                      \
        for (int i = 0; i < 4; i++) {                                          \
            int idx = tid + 256 * i;                                           \
            int r = idx >> 4, o = idx & 15;                                    \
            uint32_t d = r * ROWP + o * 16;                                    \
            size_t s = rb + (size_t)r * HD + o * 8;                            \
            cp16(base + d,             kh + s);                                \
            cp16(base + KTILE + d,     kl + s);                                \
            cp16(base + 2 * KTILE + d, vh + s);                                \
        }                                                                      \
        cp_commit();                                                           \
    } while (0)

    LOAD_KV(0, 0);
    LOAD_KV(1, 1);

    const int wq0 = w * 16;
    const uint32_t qoff = (uint32_t)(wq0 + (lane & 15)) * ROWP + ((lane >> 4) << 4);
    const uint32_t krow = (lane & 7) + ((lane >> 4) << 3);
    const uint32_t kcb  = ((lane >> 3) & 1) << 4;
    const uint32_t vrow = (lane & 7) + (((lane >> 3) & 1) << 3);
    const uint32_t vcb  = (lane >> 4) << 4;

    float m0 = -1e30f, m1 = -1e30f, l0 = 0.f, l1 = 0.f;
    float o[16][4];
#pragma unroll
    for (int t = 0; t < 16; t++)
#pragma unroll
        for (int e = 0; e < 4; e++) o[t][e] = 0.f;

    const int NT = SEQ / 64;
    for (int t = 0; t < NT; t++) {
        if (t < NT - 2) asm volatile("cp.async.wait_group 1;" ::: "memory");
        else            asm volatile("cp.async.wait_group 0;" ::: "memory");
        __syncthreads();

        const uint32_t kb = kvb0 + (t & 1) * STG;

        float sc[8][4];
#pragma unroll
        for (int tt = 0; tt < 8; tt++)
#pragma unroll
            for (int e = 0; e < 4; e++) sc[tt][e] = 0.f;

#pragma unroll
        for (int kg = 0; kg < 8; kg++) {
            uint32_t aqh[4], aql4[4];
            ldsm4(aqh,  qsh + qoff + kg * 32);
            ldsm4(aql4, qsl + qoff + kg * 32);
#pragma unroll
            for (int ng = 0; ng < 4; ng++) {
                uint32_t kh4[4], kl4[4];
                uint32_t ka = kb + (ng * 16 + krow) * ROWP + kcb + kg * 32;
                ldsm4(kh4, ka);
                ldsm4(kl4, ka + KTILE);
                mma_f16(sc[2 * ng],     aqh,  kh4[0], kh4[1]);
                mma_f16(sc[2 * ng + 1], aqh,  kh4[2], kh4[3]);
                mma_f16(sc[2 * ng],     aqh,  kl4[0], kl4[1]);
                mma_f16(sc[2 * ng + 1], aqh,  kl4[2], kl4[3]);
                mma_f16(sc[2 * ng],     aql4, kh4[0], kh4[1]);
                mma_f16(sc[2 * ng + 1], aql4, kh4[2], kh4[3]);
            }
        }

        float mx0 = -1e30f, mx1 = -1e30f;
#pragma unroll
        for (int tt = 0; tt < 8; tt++) {
            mx0 = fmaxf(mx0, fmaxf(sc[tt][0], sc[tt][1]));
            mx1 = fmaxf(mx1, fmaxf(sc[tt][2], sc[tt][3]));
        }
        mx0 = fmaxf(mx0, __shfl_xor_sync(0xffffffffu, mx0, 1));
        mx0 = fmaxf(mx0, __shfl_xor_sync(0xffffffffu, mx0, 2));
        mx1 = fmaxf(mx1, __shfl_xor_sync(0xffffffffu, mx1, 1));
        mx1 = fmaxf(mx1, __shfl_xor_sync(0xffffffffu, mx1, 2));

        float nm0 = fmaxf(m0, mx0), nm1 = fmaxf(m1, mx1);
        float c0 = exp2p(m0 - nm0), c1 = exp2p(m1 - nm1);
        m0 = nm0; m1 = nm1;

        uint32_t pah[4][4];
        float rs0 = 0.f, rs1 = 0.f;
#pragma unroll
        for (int tt = 0; tt < 8; tt++) {
            float p0 = exp2p(sc[tt][0] - m0);
            float p1 = exp2p(sc[tt][1] - m0);
            float p2 = exp2p(sc[tt][2] - m1);
            float p3 = exp2p(sc[tt][3] - m1);
            rs0 += p0 + p1;
            rs1 += p2 + p3;
            int g = tt >> 1, ri = (tt & 1) * 2;
            pah[g][ri]     = packh2(p0, p1);
            pah[g][ri + 1] = packh2(p2, p3);
        }
        rs0 += __shfl_xor_sync(0xffffffffu, rs0, 1);
        rs0 += __shfl_xor_sync(0xffffffffu, rs0, 2);
        rs1 += __shfl_xor_sync(0xffffffffu, rs1, 1);
        rs1 += __shfl_xor_sync(0xffffffffu, rs1, 2);
        l0 = l0 * c0 + rs0;
        l1 = l1 * c1 + rs1;

#pragma unroll
        for (int tt = 0; tt < 16; tt++) {
            o[tt][0] *= c0; o[tt][1] *= c0;
            o[tt][2] *= c1; o[tt][3] *= c1;
        }

#pragma unroll
        for (int g = 0; g < 4; g++) {
#pragma unroll
            for (int dg = 0; dg < 8; dg++) {
                uint32_t v4[4];
                uint32_t va = kb + 2 * KTILE + (g * 16 + vrow) * ROWP + vcb + dg * 32;
                ldsm4t(v4, va);
                mma_f16(o[2 * dg],     pah[g], v4[0], v4[1]);
                mma_f16(o[2 * dg + 1], pah[g], v4[2], v4[3]);
            }
        }
        __syncthreads();
        if (t + 2 < NT) LOAD_KV(t & 1, t + 2);
    }
#undef LOAD_KV

    float il0 = 1.0f / l0, il1 = 1.0f / l1;
    int b = bh >> 4, h = bh & 15;
    int s0 = qt * 128 + wq0 + (lane >> 2);
    int s1 = s0 + 8;
    size_t row0 = ((size_t)b * SEQ + s0) * HIDDEN + h * HD;
    size_t row1 = ((size_t)b * SEQ + s1) * HIDDEN + h * HD;
    int dc = (lane & 3) * 2;
#pragma unroll
    for (int tt = 0; tt < 16; tt++) {
        int d = tt * 8 + dc;
        *(uint32_t*)(outh + row0 + d) = packh2(o[tt][0] * il0, o[tt][1] * il0);
        *(uint32_t*)(outh + row1 + d) = packh2(o[tt][2] * il1, o[tt][3] * il1);
    }
}

// ---------------------------------------------------------------------------
extern "C" void kernel_launch(void* const* d_in, const int* in_sizes, int n_in,
                              void* d_out, int out_size)
{
    const float* hidden = (const float*)d_in[0];
    const int*   posids = (const int*)d_in[1];
    const float* wq = (const float*)d_in[2];
    const float* wk = (const float*)d_in[3];
    const float* wv = (const float*)d_in[4];
    const float* wo = (const float*)d_in[5];
    float* out = (float*)d_out;

    __half *ah, *al, *whi, *wlo, *qhp, *qlp, *khp, *klp, *vhp;
    float *cs, *sn;
    cudaGetSymbolAddress((void**)&ah, g_ah);
    cudaGetSymbolAddress((void**)&al, g_al);
    cudaGetSymbolAddress((void**)&whi, g_whi);
    cudaGetSymbolAddress((void**)&wlo, g_wlo);
    cudaGetSymbolAddress((void**)&qhp, g_qh);
    cudaGetSymbolAddress((void**)&qlp, g_ql);
    cudaGetSymbolAddress((void**)&khp, g_kh);
    cudaGetSymbolAddress((void**)&klp, g_kl);
    cudaGetSymbolAddress((void**)&vhp, g_vh);
    cudaGetSymbolAddress((void**)&cs, g_cs);
    cudaGetSymbolAddress((void**)&sn, g_sn);
    const size_t wstep = (size_t)HIDDEN * HIDDEN;

    cudaFuncSetAttribute(gemm_qk3, cudaFuncAttributeMaxDynamicSharedMemorySize, GEMM_QK_SMEM);
    cudaFuncSetAttribute(gemm_hmma1<2>, cudaFuncAttributeMaxDynamicSharedMemorySize, GEMM1_SMEM);
    cudaFuncSetAttribute(gemm_hmma1<0>, cudaFuncAttributeMaxDynamicSharedMemorySize, GEMM1_SMEM);
    cudaFuncSetAttribute(attn_tc, cudaFuncAttributeMaxDynamicSharedMemorySize, ATTN_SMEM);

    // packs + rope table
    pack_hl<<<(MROWS * HIDDEN) / 1024, 256>>>(hidden, ah, al);
    dim3 wg(HIDDEN / 32, HIDDEN / 32);
    pack_wT<1><<<wg, dim3(32, 8)>>>(wq, whi + 0 * wstep, wlo + 0 * wstep);
    pack_wT<1><<<wg, dim3(32, 8)>>>(wk, whi + 1 * wstep, wlo + 1 * wstep);
    pack_wT<0><<<wg, dim3(32, 8)>>>(wv, whi + 2 * wstep, nullptr);
    pack_wT<0><<<wg, dim3(32, 8)>>>(wo, whi + 3 * wstep, nullptr);
    rope_tab<<<(SEQ * 64) / 256, 256>>>(posids, cs, sn);

    // fused Q+K projection with RoPE epilogue -> fp16 hi/lo (b,h,s,d)
    gemm_qk3<<<dim3(NH, MROWS / 128, 2), 256, GEMM_QK_SMEM>>>(
        ah, al, whi, wlo, cs, sn, qhp, qlp, khp, klp);

    // V projection (1-term) -> fp16 (b,h,s,d)
    dim3 gg(HIDDEN / 128, MROWS / 128);
    gemm_hmma1<2><<<gg, 256, GEMM1_SMEM>>>(ah, whi + 2 * wstep, vhp);

    // attention -> single fp16 into O-proj A buffer
    dim3 ag(SEQ / 128, BATCH * NH);
    attn_tc<<<ag, 256, ATTN_SMEM>>>(qhp, qlp, khp, klp, vhp, ah);

    // O projection (1-term, fp32 row-major out)
    gemm_hmma1<0><<<gg, 256, GEMM1_SMEM>>>(ah, whi + 3 * wstep, out);
}